// round 8
// baseline (speedup 1.0000x reference)
#include <cuda_runtime.h>

// ---------------- Problem constants ----------------
#define NB    8
#define SD    512
#define CIN   512
#define COUT  512
#define CPG   64
#define NG    8
#define HH    64
#define WW    64
#define HWSZ  4096
#define KDK   4608
#define ODK   32768
#define NCOL  72
#define BCOLS 80      // 8 groups * 10 slots (9 valid + 1 pad)

typedef unsigned long long ull;

// ---------------- Device scratch ----------------
__device__ float g_pooled[NB * SD];
__device__ float g_pwkn[NB * ODK];
__device__ float g_pwbias[NB * COUT];
__device__ __align__(16) ull g_Bdup[KDK * BCOLS];      // dup-packed im2col of style
__device__ float g_dwT[NB * CPG * 9 * COUT];           // [n][ci][k][co]

// ---------------- f32x2 helpers ----------------
__device__ __forceinline__ ull pk2(float lo, float hi) {
    ull r;
    asm("mov.b64 %0, {%1, %2};" : "=l"(r) : "f"(lo), "f"(hi));
    return r;
}
__device__ __forceinline__ void upk2(ull v, float& lo, float& hi) {
    asm("mov.b64 {%0, %1}, %2;" : "=f"(lo), "=f"(hi) : "l"(v));
}
__device__ __forceinline__ void fma2(ull& d, ull a, ull b) {
    asm("fma.rn.f32x2 %0, %1, %2, %0;" : "+l"(d) : "l"(a), "l"(b));
}

// ---------------- K0: 3x3 avg pool ----------------
__global__ void k_pool(const float* __restrict__ style) {
    int i = blockIdx.x * blockDim.x + threadIdx.x;
    if (i >= NB * SD) return;
    const float* p = style + (size_t)i * 25;
    float s = 0.f;
#pragma unroll
    for (int y = 0; y < 3; y++)
#pragma unroll
        for (int x = 0; x < 3; x++)
            s += p[y * 5 + x];
    g_pooled[i] = s * (1.0f / 9.0f);
}

// ---------------- K0b: build dup-packed im2col B [K][80] ----------------
__global__ void k_buildB(const float* __restrict__ style) {
    int i = blockIdx.x * blockDim.x + threadIdx.x;
    if (i >= KDK * BCOLS) return;
    int k = i / BCOLS, s = i % BCOLS;
    int nt = s / 10, j = s % 10;
    float v = 0.f;
    if (j < 9) {
        int y = j / 3, x = j % 3;
        int sc = k / 9, r = k % 9, dy = r / 3, dx = r % 3;
        v = style[((size_t)(nt * SD + sc) * 5 + (y + dy)) * 5 + (x + dx)];
    }
    g_Bdup[i] = pk2(v, v);
}

// ---------------- K1: pooled GEMVs ----------------
__global__ void __launch_bounds__(256) k_pw(const float* __restrict__ Wpwk, const float* __restrict__ bpwk,
                                            const float* __restrict__ Wpwb, const float* __restrict__ bpwb) {
    __shared__ float ps[NB * SD];
    int tid = threadIdx.x;
    for (int i = tid; i < NB * SD; i += 256) ps[i] = g_pooled[i];
    __syncthreads();

    int r = blockIdx.x * 256 + tid;
    if (r >= ODK + COUT) return;
    bool isk = (r < ODK);
    int rr = isk ? r : (r - ODK);
    const float* w = isk ? (Wpwk + (size_t)r * SD) : (Wpwb + (size_t)rr * SD);
    float bias = isk ? bpwk[r] : bpwb[rr];

    float acc[NB];
#pragma unroll
    for (int n = 0; n < NB; n++) acc[n] = 0.f;

    for (int s = 0; s < SD; s += 4) {
        float4 wv = *(const float4*)(w + s);
#pragma unroll
        for (int n = 0; n < NB; n++) {
            const float* pp = &ps[n * SD + s];
            acc[n] += wv.x * pp[0] + wv.y * pp[1] + wv.z * pp[2] + wv.w * pp[3];
        }
    }
    if (isk) {
#pragma unroll
        for (int n = 0; n < NB; n++) g_pwkn[(size_t)n * ODK + r] = acc[n] + bias;
    } else {
#pragma unroll
        for (int n = 0; n < NB; n++) g_pwbias[n * COUT + rr] = acc[n] + bias;
    }
}

// ---------------- K2: dk GEMM (32768 x 72 x 4608) ----------------
// 128 threads, MT=64 rows. Warp w covers rows w*16..w*16+15.
// Lane = (m_sub = lane&3) x (n_sub = lane>>2): 4 rows (2 M-pairs) x 9 cols.
// A LDS is 4-distinct-address broadcast (~1 wf); B LDS conflict-free (1 wf each).
#define MTD 64
#define KT  32
#define ASTR 68

__global__ void __launch_bounds__(128) k_dk(const float* __restrict__ Wdk, const float* __restrict__ bdk) {
    __shared__ __align__(16) float As[KT * ASTR];   // [k][m], 8704 B
    __shared__ __align__(16) ull Bsd[KT * BCOLS];   // 20480 B

    int tid = threadIdx.x;
    int m0 = blockIdx.x * MTD;
    int wid = tid >> 5;
    int lane = tid & 31;
    int m_sub = lane & 3;
    int n_sub = lane >> 2;          // 0..7
    int mrow = wid * 16 + m_sub * 4;  // this thread's first row within block tile

    ull acc[2][9];
#pragma unroll
    for (int i = 0; i < 2; i++)
#pragma unroll
        for (int j = 0; j < 9; j++) acc[i][j] = 0ULL;

    int arow = tid >> 1;          // 0..63
    int kbase = (tid & 1) * 16;   // 0 or 16
    const float* ap = Wdk + (size_t)(m0 + arow) * KDK + kbase;
    float4 pa[4];
#pragma unroll
    for (int q = 0; q < 4; q++) pa[q] = *(const float4*)(ap + q * 4);

    for (int k0 = 0; k0 < KDK; k0 += KT) {
        __syncthreads();  // previous tile compute done
        // store A tile transposed
#pragma unroll
        for (int q = 0; q < 4; q++) {
            int k = kbase + q * 4;
            As[(k + 0) * ASTR + arow] = pa[q].x;
            As[(k + 1) * ASTR + arow] = pa[q].y;
            As[(k + 2) * ASTR + arow] = pa[q].z;
            As[(k + 3) * ASTR + arow] = pa[q].w;
        }
        // copy dup-packed B tile (L2-resident): 2560 ull / 128 thr = 20 each
        const ull* bsrc = g_Bdup + (size_t)k0 * BCOLS;
#pragma unroll
        for (int q = 0; q < 20; q++) Bsd[tid + 128 * q] = bsrc[tid + 128 * q];
        // prefetch next A tile
        if (k0 + KT < KDK) {
            ap += KT;
#pragma unroll
            for (int q = 0; q < 4; q++) pa[q] = *(const float4*)(ap + q * 4);
        }
        __syncthreads();

#pragma unroll 8
        for (int kk = 0; kk < KT; kk++) {
            ulonglong2 av = *(const ulonglong2*)&As[kk * ASTR + mrow];  // two M-pairs
            const ull* br = &Bsd[kk * BCOLS + n_sub * 10];
            ulonglong2 b01 = *(const ulonglong2*)(br);
            ulonglong2 b23 = *(const ulonglong2*)(br + 2);
            ulonglong2 b45 = *(const ulonglong2*)(br + 4);
            ulonglong2 b67 = *(const ulonglong2*)(br + 6);
            ull b8 = br[8];
            fma2(acc[0][0], av.x, b01.x); fma2(acc[1][0], av.y, b01.x);
            fma2(acc[0][1], av.x, b01.y); fma2(acc[1][1], av.y, b01.y);
            fma2(acc[0][2], av.x, b23.x); fma2(acc[1][2], av.y, b23.x);
            fma2(acc[0][3], av.x, b23.y); fma2(acc[1][3], av.y, b23.y);
            fma2(acc[0][4], av.x, b45.x); fma2(acc[1][4], av.y, b45.x);
            fma2(acc[0][5], av.x, b45.y); fma2(acc[1][5], av.y, b45.y);
            fma2(acc[0][6], av.x, b67.x); fma2(acc[1][6], av.y, b67.x);
            fma2(acc[0][7], av.x, b67.y); fma2(acc[1][7], av.y, b67.y);
            fma2(acc[0][8], av.x, b8);    fma2(acc[1][8], av.y, b8);
        }
    }

    // scatter: pair i covers rows o0+2i, o0+2i+1 ; col group n=n_sub, kidx=j
    int o0 = m0 + mrow;
    int co = o0 >> 6, ci0 = o0 & 63;   // quad stays inside one co
#pragma unroll
    for (int i = 0; i < 2; i++) {
        float bv0 = bdk[o0 + 2 * i], bv1 = bdk[o0 + 2 * i + 1];
#pragma unroll
        for (int j = 0; j < 9; j++) {
            float lo, hi;
            upk2(acc[i][j], lo, hi);
            size_t base = ((size_t)((n_sub * CPG + ci0 + 2 * i) * 9 + j)) * COUT + co;
            g_dwT[base] = lo + bv0;
            g_dwT[base + 9 * COUT] = hi + bv1;
        }
    }
}

// ---------------- K3: fused depthwise+pointwise, double-buffered prefetch ----------------
#define IN_OFF   (CPG * 4 * WW)                 // 16384 floats (depth tile)
#define BUFSZ    816                            // (408 main + 408 shifted) per buffer
#define PW_OFF   (IN_OFF + 2 * BUFSZ)           // + 1632
#define SMEM_CONV ((PW_OFF + CPG * CPG) * 4)    // 88448 B

__device__ __forceinline__ int refl(int i) {
    return i < 0 ? -i : (i > 63 ? 126 - i : i);
}

__global__ void __launch_bounds__(256, 2) k_conv(const float* __restrict__ pred, float* __restrict__ out) {
    extern __shared__ __align__(16) float sm[];
    float* depth_s = sm;
    float* in_base = sm + IN_OFF;   // two buffers of [408 main | 408 shifted]
    float* pw_s    = sm + PW_OFF;

    int tid = threadIdx.x;
    int co = tid & 63;
    int hl = tid >> 6;
    int rb = blockIdx.x, g = blockIdx.y, n = blockIdx.z;
    int h0 = rb * 4;

    const float* base = pred + (size_t)(n * CIN + g * CPG) * HWSZ;

    // preload pw weights transposed (visible after first barrier)
    for (int i = tid; i < CPG * CPG; i += 256) {
        int cm = i >> 6, c = i & 63;
        pw_s[i] = g_pwkn[(size_t)n * ODK + (g * CPG + c) * CPG + cm];
    }

    // loader geometry: positions idx in [0, 396): r = idx/66, c = idx%66
    int i0 = tid, i1 = tid + 256;
    int r0 = i0 / 66, c0p = i0 % 66;
    int r1 = i1 / 66, c1p = i1 % 66;
    bool v1 = (i1 < 396);
    int goff0 = refl(h0 + r0 - 1) * WW + refl(c0p - 1);
    int goff1 = v1 ? (refl(h0 + r1 - 1) * WW + refl(c1p - 1)) : 0;
    int s0 = r0 * 68 + c0p;
    int s1 = r1 * 68 + c1p;

    // prefetch ci=0 input + weights
    float q0 = base[goff0];
    float q1 = v1 ? base[goff1] : 0.f;
    const float* wp = g_dwT + ((size_t)(n * CPG) * 9) * COUT + (g * CPG + co);
    float dcur[9], dnxt[9];
#pragma unroll
    for (int k = 0; k < 9; k++) dcur[k] = wp[k * COUT];

    ull acc2[32];
#pragma unroll
    for (int i = 0; i < 32; i++) acc2[i] = 0ULL;

    for (int ci = 0; ci < CPG; ci++) {
        float* ia = in_base + (ci & 1) * BUFSZ;
        float* ib = ia + 408;
        ia[s0] = q0;
        if (c0p) ib[s0 - 1] = q0;
        if (v1) {
            ia[s1] = q1;
            if (c1p) ib[s1 - 1] = q1;
        }
        __syncthreads();

        // prefetch ci+1 input + weights (overlaps compute)
        if (ci + 1 < CPG) {
            const float* pl = base + (size_t)(ci + 1) * HWSZ;
            q0 = pl[goff0];
            q1 = v1 ? pl[goff1] : 0.f;
            const float* wn = wp + (size_t)(ci + 1) * 9 * COUT;
#pragma unroll
            for (int k = 0; k < 9; k++) dnxt[k] = wn[k * COUT];
        }

        // compute depthwise for this ci
#pragma unroll
        for (int kh = 0; kh < 3; kh++) {
            const float* row  = &ia[(hl + kh) * 68];
            const float* rowB = row + 408;
            ull w0 = pk2(dcur[kh * 3 + 0], dcur[kh * 3 + 0]);
            ull w1 = pk2(dcur[kh * 3 + 1], dcur[kh * 3 + 1]);
            ull w2 = pk2(dcur[kh * 3 + 2], dcur[kh * 3 + 2]);
#pragma unroll
            for (int c0 = 0; c0 < 64; c0 += 16) {
                const ull* ra = (const ull*)(row + c0);
                ulonglong2 a01 = *(const ulonglong2*)(ra);
                ulonglong2 a23 = *(const ulonglong2*)(ra + 2);
                ulonglong2 a45 = *(const ulonglong2*)(ra + 4);
                ulonglong2 a67 = *(const ulonglong2*)(ra + 6);
                ull a8 = ra[8];
                const ull* rbp = (const ull*)(rowB + c0);
                ulonglong2 b01 = *(const ulonglong2*)(rbp);
                ulonglong2 b23 = *(const ulonglong2*)(rbp + 2);
                ulonglong2 b45 = *(const ulonglong2*)(rbp + 4);
                ulonglong2 b67 = *(const ulonglong2*)(rbp + 6);
                int p = c0 >> 1;
                fma2(acc2[p + 0], w0, a01.x); fma2(acc2[p + 0], w1, b01.x); fma2(acc2[p + 0], w2, a01.y);
                fma2(acc2[p + 1], w0, a01.y); fma2(acc2[p + 1], w1, b01.y); fma2(acc2[p + 1], w2, a23.x);
                fma2(acc2[p + 2], w0, a23.x); fma2(acc2[p + 2], w1, b23.x); fma2(acc2[p + 2], w2, a23.y);
                fma2(acc2[p + 3], w0, a23.y); fma2(acc2[p + 3], w1, b23.y); fma2(acc2[p + 3], w2, a45.x);
                fma2(acc2[p + 4], w0, a45.x); fma2(acc2[p + 4], w1, b45.x); fma2(acc2[p + 4], w2, a45.y);
                fma2(acc2[p + 5], w0, a45.y); fma2(acc2[p + 5], w1, b45.y); fma2(acc2[p + 5], w2, a67.x);
                fma2(acc2[p + 6], w0, a67.x); fma2(acc2[p + 6], w1, b67.x); fma2(acc2[p + 6], w2, a67.y);
                fma2(acc2[p + 7], w0, a67.y); fma2(acc2[p + 7], w1, b67.y); fma2(acc2[p + 7], w2, a8);
            }
        }
#pragma unroll
        for (int k = 0; k < 9; k++) dcur[k] = dnxt[k];
    }

    // stash depth tile
    __syncthreads();
    {
        ull* dst = (ull*)(depth_s + (co * 4 + hl) * 64);
#pragma unroll
        for (int i = 0; i < 32; i++) dst[i] = acc2[i];
    }
    __syncthreads();

    // pointwise (reuse acc2 as output accumulator)
#pragma unroll
    for (int i = 0; i < 32; i++) acc2[i] = 0ULL;
    for (int cm = 0; cm < CPG; cm++) {
        float v = pw_s[cm * 64 + co];
        ull vp = pk2(v, v);
        const ulonglong2* ds = (const ulonglong2*)(depth_s + (cm * 4 + hl) * 64);
#pragma unroll
        for (int i = 0; i < 16; i++) {
            ulonglong2 t = ds[i];
            fma2(acc2[2 * i],     vp, t.x);
            fma2(acc2[2 * i + 1], vp, t.y);
        }
    }

    float bias = g_pwbias[n * COUT + g * CPG + co];
    float* op = out + (((size_t)(n * COUT + g * CPG + co)) * HH + (h0 + hl)) * WW;
#pragma unroll
    for (int i = 0; i < 16; i++) {
        float x0, x1, x2, x3;
        upk2(acc2[2 * i], x0, x1);
        upk2(acc2[2 * i + 1], x2, x3);
        *(float4*)(op + 4 * i) = make_float4(x0 + bias, x1 + bias, x2 + bias, x3 + bias);
    }
}

// ---------------- Launch ----------------
extern "C" void kernel_launch(void* const* d_in, const int* in_sizes, int n_in,
                              void* d_out, int out_size) {
    const float* style = (const float*)d_in[0];
    const float* pred  = (const float*)d_in[1];
    const float* Wdk   = (const float*)d_in[2];
    const float* bdk   = (const float*)d_in[3];
    const float* Wpwk  = (const float*)d_in[4];
    const float* bpwk  = (const float*)d_in[5];
    const float* Wpwb  = (const float*)d_in[6];
    const float* bpwb  = (const float*)d_in[7];
    float* out = (float*)d_out;

    cudaFuncSetAttribute(k_conv, cudaFuncAttributeMaxDynamicSharedMemorySize, SMEM_CONV);

    k_pool<<<(NB * SD + 255) / 256, 256>>>(style);
    k_buildB<<<(KDK * BCOLS + 255) / 256, 256>>>(style);
    k_pw<<<(ODK + COUT + 255) / 256, 256>>>(Wpwk, bpwk, Wpwb, bpwb);
    k_dk<<<ODK / MTD, 128>>>(Wdk, bdk);
    k_conv<<<dim3(HH / 4, NG, NB), 256, SMEM_CONV>>>(pred, out);
}

// round 10
// speedup vs baseline: 1.3057x; 1.3057x over previous
#include <cuda_runtime.h>
#include <cuda_bf16.h>
#include <cstdint>

// ---------------- Problem constants ----------------
#define NB    8
#define SD    512
#define CIN   512
#define COUT  512
#define CPG   64
#define NG    8
#define HH    64
#define WW    64
#define HWSZ  4096
#define KDK   4608
#define ODK   32768
#define NCOL  72
#define NSTEP 288          // KDK / 16
#define NTIL  9            // 72 / 8

typedef unsigned long long ull;

// ---------------- Device scratch ----------------
__device__ float g_pooled[NB * SD];
__device__ float g_pwkn[NB * ODK];
__device__ float g_pwbias[NB * COUT];
__device__ __align__(16) uint4 g_Bfrag[NSTEP * NTIL * 32];   // 1.33 MB: {bhi0,bhi1,blo0,blo1} per lane
__device__ float g_dwT[NB * CPG * 9 * COUT];                 // [n][ci][k][co]

// ---------------- f32x2 helpers (k_conv) ----------------
__device__ __forceinline__ ull pk2(float lo, float hi) {
    ull r;
    asm("mov.b64 %0, {%1, %2};" : "=l"(r) : "f"(lo), "f"(hi));
    return r;
}
__device__ __forceinline__ void upk2(ull v, float& lo, float& hi) {
    asm("mov.b64 {%0, %1}, %2;" : "=f"(lo), "=f"(hi) : "l"(v));
}
__device__ __forceinline__ void fma2(ull& d, ull a, ull b) {
    asm("fma.rn.f32x2 %0, %1, %2, %0;" : "+l"(d) : "l"(a), "l"(b));
}

// ---------------- mma.sync helper ----------------
__device__ __forceinline__ void mma16816(float* c, const uint32_t* a, uint32_t b0, uint32_t b1) {
    asm volatile(
        "mma.sync.aligned.m16n8k16.row.col.f32.bf16.bf16.f32 "
        "{%0,%1,%2,%3}, {%4,%5,%6,%7}, {%8,%9}, {%0,%1,%2,%3};"
        : "+f"(c[0]), "+f"(c[1]), "+f"(c[2]), "+f"(c[3])
        : "r"(a[0]), "r"(a[1]), "r"(a[2]), "r"(a[3]), "r"(b0), "r"(b1));
}
__device__ __forceinline__ uint32_t bf2u(__nv_bfloat162 h) {
    return *(const uint32_t*)&h;
}

// ---------------- K0: 3x3 avg pool ----------------
__global__ void k_pool(const float* __restrict__ style) {
    int i = blockIdx.x * blockDim.x + threadIdx.x;
    if (i >= NB * SD) return;
    const float* p = style + (size_t)i * 25;
    float s = 0.f;
#pragma unroll
    for (int y = 0; y < 3; y++)
#pragma unroll
        for (int x = 0; x < 3; x++)
            s += p[y * 5 + x];
    g_pooled[i] = s * (1.0f / 9.0f);
}

// ---------------- K0b: build B fragments (mma m16n8k16 col-major layout) ----------------
__device__ __forceinline__ float bval(const float* style, int n, int k) {
    int batch = n / 9, q = n % 9;
    int y = q / 3, x = q % 3;
    int sc = k / 9, rr = k % 9;
    int dy = rr / 3, dx = rr % 3;
    return style[((size_t)(batch * SD + sc) * 5 + (y + dy)) * 5 + (x + dx)];
}

__global__ void k_buildB(const float* __restrict__ style) {
    int i = blockIdx.x * blockDim.x + threadIdx.x;
    if (i >= NSTEP * NTIL * 32) return;
    int lane = i & 31;
    int t = i >> 5;
    int nt = t % NTIL;
    int s = t / NTIL;
    int n = nt * 8 + (lane >> 2);          // n <= 71 always
    int kb = s * 16 + (lane & 3) * 2;
    int kk[4] = {kb, kb + 1, kb + 8, kb + 9};
    float v[4];
#pragma unroll
    for (int q = 0; q < 4; q++) v[q] = bval(style, n, kk[q]);
    __nv_bfloat16 h[4];
    float l[4];
#pragma unroll
    for (int q = 0; q < 4; q++) {
        h[q] = __float2bfloat16(v[q]);
        l[q] = v[q] - __bfloat162float(h[q]);
    }
    uint4 out;
    out.x = bf2u(__nv_bfloat162(h[0], h[1]));
    out.y = bf2u(__nv_bfloat162(h[2], h[3]));
    out.z = bf2u(__floats2bfloat162_rn(l[0], l[1]));
    out.w = bf2u(__floats2bfloat162_rn(l[2], l[3]));
    g_Bfrag[t * 32 + lane] = out;
}

// ---------------- K1: pooled GEMVs ----------------
__global__ void __launch_bounds__(256) k_pw(const float* __restrict__ Wpwk, const float* __restrict__ bpwk,
                                            const float* __restrict__ Wpwb, const float* __restrict__ bpwb) {
    __shared__ float ps[NB * SD];
    int tid = threadIdx.x;
    for (int i = tid; i < NB * SD; i += 256) ps[i] = g_pooled[i];
    __syncthreads();

    int r = blockIdx.x * 256 + tid;
    if (r >= ODK + COUT) return;
    bool isk = (r < ODK);
    int rr = isk ? r : (r - ODK);
    const float* w = isk ? (Wpwk + (size_t)r * SD) : (Wpwb + (size_t)rr * SD);
    float bias = isk ? bpwk[r] : bpwb[rr];

    float acc[NB];
#pragma unroll
    for (int n = 0; n < NB; n++) acc[n] = 0.f;

    for (int s = 0; s < SD; s += 4) {
        float4 wv = *(const float4*)(w + s);
#pragma unroll
        for (int n = 0; n < NB; n++) {
            const float* pp = &ps[n * SD + s];
            acc[n] += wv.x * pp[0] + wv.y * pp[1] + wv.z * pp[2] + wv.w * pp[3];
        }
    }
    if (isk) {
#pragma unroll
        for (int n = 0; n < NB; n++) g_pwkn[(size_t)n * ODK + r] = acc[n] + bias;
    } else {
#pragma unroll
        for (int n = 0; n < NB; n++) g_pwbias[n * COUT + rr] = acc[n] + bias;
    }
}

// ---------------- K2: dk GEMM via mma.sync bf16-split ----------------
// 128 threads = 4 warps x 16 rows. Grid 512. A fragments straight from GMEM,
// B fragments from precomputed table. 27 MMAs per warp per k16-step.
__global__ void __launch_bounds__(128) k_dk(const float* __restrict__ Wdk, const float* __restrict__ bdk) {
    int tid = threadIdx.x;
    int wid = tid >> 5, lane = tid & 31;
    int m0 = blockIdx.x * 64 + wid * 16;
    int r0 = m0 + (lane >> 2);
    int kc = (lane & 3) * 2;

    const float* a0p = Wdk + (size_t)r0 * KDK + kc;          // row r0
    const float* a1p = a0p + (size_t)8 * KDK;                // row r0+8

    float acc[NTIL][4];
#pragma unroll
    for (int nt = 0; nt < NTIL; nt++)
#pragma unroll
        for (int q = 0; q < 4; q++) acc[nt][q] = 0.f;

    float2 pa[2][4];
    uint4 pb[2][NTIL];
    // preload s=0
    pa[0][0] = *(const float2*)(a0p);
    pa[0][1] = *(const float2*)(a1p);
    pa[0][2] = *(const float2*)(a0p + 8);
    pa[0][3] = *(const float2*)(a1p + 8);
    {
        const uint4* bp = g_Bfrag + lane;
#pragma unroll
        for (int nt = 0; nt < NTIL; nt++) pb[0][nt] = bp[nt * 32];
    }

#pragma unroll 2
    for (int s = 0; s < NSTEP; s++) {
        int cb = s & 1, nb = cb ^ 1;
        if (s + 1 < NSTEP) {
            const float* ap = a0p + (size_t)(s + 1) * 16;
            pa[nb][0] = *(const float2*)(ap);
            pa[nb][1] = *(const float2*)(ap + (size_t)8 * KDK);
            pa[nb][2] = *(const float2*)(ap + 8);
            pa[nb][3] = *(const float2*)(ap + (size_t)8 * KDK + 8);
            const uint4* bp = g_Bfrag + (size_t)(s + 1) * NTIL * 32 + lane;
#pragma unroll
            for (int nt = 0; nt < NTIL; nt++) pb[nb][nt] = bp[nt * 32];
        }
        // convert A to bf16 hi/lo fragments
        uint32_t ahi[4], alo[4];
#pragma unroll
        for (int q = 0; q < 4; q++) {
            float2 f = pa[cb][q];
            __nv_bfloat162 h = __floats2bfloat162_rn(f.x, f.y);
            ahi[q] = bf2u(h);
            float lx = f.x - __low2float(h);
            float ly = f.y - __high2float(h);
            alo[q] = bf2u(__floats2bfloat162_rn(lx, ly));
        }
#pragma unroll
        for (int nt = 0; nt < NTIL; nt++) {
            uint4 b = pb[cb][nt];
            mma16816(acc[nt], ahi, b.x, b.y);   // hi * hi
            mma16816(acc[nt], ahi, b.z, b.w);   // hi * lo
            mma16816(acc[nt], alo, b.x, b.y);   // lo * hi
        }
    }

    // epilogue: c0,c1 -> (r0, col, col+1); c2,c3 -> (r0+8, col, col+1)
    int o0 = r0, o1 = r0 + 8;
    float bv0 = bdk[o0], bv1 = bdk[o1];
    int co0 = o0 >> 6, ci0 = o0 & 63;
    int co1 = o1 >> 6, ci1 = o1 & 63;
#pragma unroll
    for (int nt = 0; nt < NTIL; nt++) {
        int colb = nt * 8 + kc;
#pragma unroll
        for (int d = 0; d < 2; d++) {
            int col = colb + d;
            int n = col / 9, j = col % 9;
            g_dwT[((size_t)((n * CPG + ci0) * 9 + j)) * COUT + co0] = acc[nt][d] + bv0;
            g_dwT[((size_t)((n * CPG + ci1) * 9 + j)) * COUT + co1] = acc[nt][2 + d] + bv1;
        }
    }
}

// ---------------- K3: fused depthwise+pointwise (unchanged, proven) ----------------
#define IN_OFF   (CPG * 4 * WW)
#define BUFSZ    816
#define PW_OFF   (IN_OFF + 2 * BUFSZ)
#define SMEM_CONV ((PW_OFF + CPG * CPG) * 4)

__device__ __forceinline__ int refl(int i) {
    return i < 0 ? -i : (i > 63 ? 126 - i : i);
}

__global__ void __launch_bounds__(256, 2) k_conv(const float* __restrict__ pred, float* __restrict__ out) {
    extern __shared__ __align__(16) float sm[];
    float* depth_s = sm;
    float* in_base = sm + IN_OFF;
    float* pw_s    = sm + PW_OFF;

    int tid = threadIdx.x;
    int co = tid & 63;
    int hl = tid >> 6;
    int rb = blockIdx.x, g = blockIdx.y, n = blockIdx.z;
    int h0 = rb * 4;

    const float* base = pred + (size_t)(n * CIN + g * CPG) * HWSZ;

    for (int i = tid; i < CPG * CPG; i += 256) {
        int cm = i >> 6, c = i & 63;
        pw_s[i] = g_pwkn[(size_t)n * ODK + (g * CPG + c) * CPG + cm];
    }

    int i0 = tid, i1 = tid + 256;
    int r0 = i0 / 66, c0p = i0 % 66;
    int r1 = i1 / 66, c1p = i1 % 66;
    bool v1 = (i1 < 396);
    int goff0 = refl(h0 + r0 - 1) * WW + refl(c0p - 1);
    int goff1 = v1 ? (refl(h0 + r1 - 1) * WW + refl(c1p - 1)) : 0;
    int s0 = r0 * 68 + c0p;
    int s1 = r1 * 68 + c1p;

    float q0 = base[goff0];
    float q1 = v1 ? base[goff1] : 0.f;
    const float* wp = g_dwT + ((size_t)(n * CPG) * 9) * COUT + (g * CPG + co);
    float dcur[9], dnxt[9];
#pragma unroll
    for (int k = 0; k < 9; k++) dcur[k] = wp[k * COUT];

    ull acc2[32];
#pragma unroll
    for (int i = 0; i < 32; i++) acc2[i] = 0ULL;

    for (int ci = 0; ci < CPG; ci++) {
        float* ia = in_base + (ci & 1) * BUFSZ;
        float* ib = ia + 408;
        ia[s0] = q0;
        if (c0p) ib[s0 - 1] = q0;
        if (v1) {
            ia[s1] = q1;
            if (c1p) ib[s1 - 1] = q1;
        }
        __syncthreads();

        if (ci + 1 < CPG) {
            const float* pl = base + (size_t)(ci + 1) * HWSZ;
            q0 = pl[goff0];
            q1 = v1 ? pl[goff1] : 0.f;
            const float* wn = wp + (size_t)(ci + 1) * 9 * COUT;
#pragma unroll
            for (int k = 0; k < 9; k++) dnxt[k] = wn[k * COUT];
        }

#pragma unroll
        for (int kh = 0; kh < 3; kh++) {
            const float* row  = &ia[(hl + kh) * 68];
            const float* rowB = row + 408;
            ull w0 = pk2(dcur[kh * 3 + 0], dcur[kh * 3 + 0]);
            ull w1 = pk2(dcur[kh * 3 + 1], dcur[kh * 3 + 1]);
            ull w2 = pk2(dcur[kh * 3 + 2], dcur[kh * 3 + 2]);
#pragma unroll
            for (int c0 = 0; c0 < 64; c0 += 16) {
                const ull* ra = (const ull*)(row + c0);
                ulonglong2 a01 = *(const ulonglong2*)(ra);
                ulonglong2 a23 = *(const ulonglong2*)(ra + 2);
                ulonglong2 a45 = *(const ulonglong2*)(ra + 4);
                ulonglong2 a67 = *(const ulonglong2*)(ra + 6);
                ull a8 = ra[8];
                const ull* rbp = (const ull*)(rowB + c0);
                ulonglong2 b01 = *(const ulonglong2*)(rbp);
                ulonglong2 b23 = *(const ulonglong2*)(rbp + 2);
                ulonglong2 b45 = *(const ulonglong2*)(rbp + 4);
                ulonglong2 b67 = *(const ulonglong2*)(rbp + 6);
                int p = c0 >> 1;
                fma2(acc2[p + 0], w0, a01.x); fma2(acc2[p + 0], w1, b01.x); fma2(acc2[p + 0], w2, a01.y);
                fma2(acc2[p + 1], w0, a01.y); fma2(acc2[p + 1], w1, b01.y); fma2(acc2[p + 1], w2, a23.x);
                fma2(acc2[p + 2], w0, a23.x); fma2(acc2[p + 2], w1, b23.x); fma2(acc2[p + 2], w2, a23.y);
                fma2(acc2[p + 3], w0, a23.y); fma2(acc2[p + 3], w1, b23.y); fma2(acc2[p + 3], w2, a45.x);
                fma2(acc2[p + 4], w0, a45.x); fma2(acc2[p + 4], w1, b45.x); fma2(acc2[p + 4], w2, a45.y);
                fma2(acc2[p + 5], w0, a45.y); fma2(acc2[p + 5], w1, b45.y); fma2(acc2[p + 5], w2, a67.x);
                fma2(acc2[p + 6], w0, a67.x); fma2(acc2[p + 6], w1, b67.x); fma2(acc2[p + 6], w2, a67.y);
                fma2(acc2[p + 7], w0, a67.y); fma2(acc2[p + 7], w1, b67.y); fma2(acc2[p + 7], w2, a8);
            }
        }
#pragma unroll
        for (int k = 0; k < 9; k++) dcur[k] = dnxt[k];
    }

    __syncthreads();
    {
        ull* dst = (ull*)(depth_s + (co * 4 + hl) * 64);
#pragma unroll
        for (int i = 0; i < 32; i++) dst[i] = acc2[i];
    }
    __syncthreads();

#pragma unroll
    for (int i = 0; i < 32; i++) acc2[i] = 0ULL;
    for (int cm = 0; cm < CPG; cm++) {
        float v = pw_s[cm * 64 + co];
        ull vp = pk2(v, v);
        const ulonglong2* ds = (const ulonglong2*)(depth_s + (cm * 4 + hl) * 64);
#pragma unroll
        for (int i = 0; i < 16; i++) {
            ulonglong2 t = ds[i];
            fma2(acc2[2 * i],     vp, t.x);
            fma2(acc2[2 * i + 1], vp, t.y);
        }
    }

    float bias = g_pwbias[n * COUT + g * CPG + co];
    float* op = out + (((size_t)(n * COUT + g * CPG + co)) * HH + (h0 + hl)) * WW;
#pragma unroll
    for (int i = 0; i < 16; i++) {
        float x0, x1, x2, x3;
        upk2(acc2[2 * i], x0, x1);
        upk2(acc2[2 * i + 1], x2, x3);
        *(float4*)(op + 4 * i) = make_float4(x0 + bias, x1 + bias, x2 + bias, x3 + bias);
    }
}

// ---------------- Launch ----------------
extern "C" void kernel_launch(void* const* d_in, const int* in_sizes, int n_in,
                              void* d_out, int out_size) {
    const float* style = (const float*)d_in[0];
    const float* pred  = (const float*)d_in[1];
    const float* Wdk   = (const float*)d_in[2];
    const float* bdk   = (const float*)d_in[3];
    const float* Wpwk  = (const float*)d_in[4];
    const float* bpwk  = (const float*)d_in[5];
    const float* Wpwb  = (const float*)d_in[6];
    const float* bpwb  = (const float*)d_in[7];
    float* out = (float*)d_out;

    cudaFuncSetAttribute(k_conv, cudaFuncAttributeMaxDynamicSharedMemorySize, SMEM_CONV);

    k_pool<<<(NB * SD + 255) / 256, 256>>>(style);
    k_buildB<<<(NSTEP * NTIL * 32 + 255) / 256, 256>>>(style);
    k_pw<<<(ODK + COUT + 255) / 256, 256>>>(Wpwk, bpwk, Wpwb, bpwb);
    k_dk<<<ODK / 64, 128>>>(Wdk, bdk);
    k_conv<<<dim3(HH / 4, NG, NB), 256, SMEM_CONV>>>(pred, out);
}

// round 11
// speedup vs baseline: 1.3501x; 1.0340x over previous
#include <cuda_runtime.h>
#include <cuda_bf16.h>
#include <cstdint>

// ---------------- Problem constants ----------------
#define NB    8
#define SD    512
#define CIN   512
#define COUT  512
#define CPG   64
#define NG    8
#define HH    64
#define WW    64
#define HWSZ  4096
#define KDK   4608
#define ODK   32768
#define NCOL  72
#define NSTEP 288          // KDK / 16
#define NTIL  9            // 72 / 8

typedef unsigned long long ull;

// ---------------- Device scratch ----------------
__device__ float g_pooled[NB * SD];
__device__ float g_pwkn[NB * ODK];
__device__ float g_pwbias[NB * COUT];
__device__ __align__(16) uint4 g_Bfrag[NSTEP * NTIL * 32];   // 1.33 MB: {bhi0,bhi1,blo0,blo1} per lane
__device__ float g_dwT[NB * CPG * 9 * COUT];                 // [n][ci][k][co]

// ---------------- f32x2 helpers (k_conv) ----------------
__device__ __forceinline__ ull pk2(float lo, float hi) {
    ull r;
    asm("mov.b64 %0, {%1, %2};" : "=l"(r) : "f"(lo), "f"(hi));
    return r;
}
__device__ __forceinline__ void upk2(ull v, float& lo, float& hi) {
    asm("mov.b64 {%0, %1}, %2;" : "=f"(lo), "=f"(hi) : "l"(v));
}
__device__ __forceinline__ void fma2(ull& d, ull a, ull b) {
    asm("fma.rn.f32x2 %0, %1, %2, %0;" : "+l"(d) : "l"(a), "l"(b));
}

// ---------------- mma.sync helper ----------------
__device__ __forceinline__ void mma16816(float* c, const uint32_t* a, uint32_t b0, uint32_t b1) {
    asm volatile(
        "mma.sync.aligned.m16n8k16.row.col.f32.bf16.bf16.f32 "
        "{%0,%1,%2,%3}, {%4,%5,%6,%7}, {%8,%9}, {%0,%1,%2,%3};"
        : "+f"(c[0]), "+f"(c[1]), "+f"(c[2]), "+f"(c[3])
        : "r"(a[0]), "r"(a[1]), "r"(a[2]), "r"(a[3]), "r"(b0), "r"(b1));
}
__device__ __forceinline__ uint32_t bf2u(__nv_bfloat162 h) {
    return *(const uint32_t*)&h;
}

// ---------------- K0: 3x3 avg pool ----------------
__global__ void k_pool(const float* __restrict__ style) {
    int i = blockIdx.x * blockDim.x + threadIdx.x;
    if (i >= NB * SD) return;
    const float* p = style + (size_t)i * 25;
    float s = 0.f;
#pragma unroll
    for (int y = 0; y < 3; y++)
#pragma unroll
        for (int x = 0; x < 3; x++)
            s += p[y * 5 + x];
    g_pooled[i] = s * (1.0f / 9.0f);
}

// ---------------- K0b: build B fragments (mma m16n8k16 col-major layout) ----------------
__device__ __forceinline__ float bval(const float* style, int n, int k) {
    int batch = n / 9, q = n % 9;
    int y = q / 3, x = q % 3;
    int sc = k / 9, rr = k % 9;
    int dy = rr / 3, dx = rr % 3;
    return style[((size_t)(batch * SD + sc) * 5 + (y + dy)) * 5 + (x + dx)];
}

__global__ void k_buildB(const float* __restrict__ style) {
    int i = blockIdx.x * blockDim.x + threadIdx.x;
    if (i >= NSTEP * NTIL * 32) return;
    int lane = i & 31;
    int t = i >> 5;
    int nt = t % NTIL;
    int s = t / NTIL;
    int n = nt * 8 + (lane >> 2);          // n <= 71 always
    int kb = s * 16 + (lane & 3) * 2;
    int kk[4] = {kb, kb + 1, kb + 8, kb + 9};
    float v[4];
#pragma unroll
    for (int q = 0; q < 4; q++) v[q] = bval(style, n, kk[q]);
    __nv_bfloat16 h[4];
    float l[4];
#pragma unroll
    for (int q = 0; q < 4; q++) {
        h[q] = __float2bfloat16(v[q]);
        l[q] = v[q] - __bfloat162float(h[q]);
    }
    uint4 out;
    out.x = bf2u(__nv_bfloat162(h[0], h[1]));
    out.y = bf2u(__nv_bfloat162(h[2], h[3]));
    out.z = bf2u(__floats2bfloat162_rn(l[0], l[1]));
    out.w = bf2u(__floats2bfloat162_rn(l[2], l[3]));
    g_Bfrag[t * 32 + lane] = out;
}

// ---------------- K1: pooled GEMVs ----------------
__global__ void __launch_bounds__(256) k_pw(const float* __restrict__ Wpwk, const float* __restrict__ bpwk,
                                            const float* __restrict__ Wpwb, const float* __restrict__ bpwb) {
    __shared__ float ps[NB * SD];
    int tid = threadIdx.x;
    for (int i = tid; i < NB * SD; i += 256) ps[i] = g_pooled[i];
    __syncthreads();

    int r = blockIdx.x * 256 + tid;
    if (r >= ODK + COUT) return;
    bool isk = (r < ODK);
    int rr = isk ? r : (r - ODK);
    const float* w = isk ? (Wpwk + (size_t)r * SD) : (Wpwb + (size_t)rr * SD);
    float bias = isk ? bpwk[r] : bpwb[rr];

    float acc[NB];
#pragma unroll
    for (int n = 0; n < NB; n++) acc[n] = 0.f;

    for (int s = 0; s < SD; s += 4) {
        float4 wv = *(const float4*)(w + s);
#pragma unroll
        for (int n = 0; n < NB; n++) {
            const float* pp = &ps[n * SD + s];
            acc[n] += wv.x * pp[0] + wv.y * pp[1] + wv.z * pp[2] + wv.w * pp[3];
        }
    }
    if (isk) {
#pragma unroll
        for (int n = 0; n < NB; n++) g_pwkn[(size_t)n * ODK + r] = acc[n] + bias;
    } else {
#pragma unroll
        for (int n = 0; n < NB; n++) g_pwbias[n * COUT + rr] = acc[n] + bias;
    }
}

// ---------------- K2: dk GEMM via mma.sync bf16-split, B staged in smem ----------------
// 128 threads = 4 warps x 16 rows (MT=64), grid 512.
// B fragments double-buffered in smem (shared by all warps); A double-buffered in regs.
__global__ void __launch_bounds__(128) k_dk(const float* __restrict__ Wdk, const float* __restrict__ bdk) {
    __shared__ __align__(16) uint4 Bs[2][NTIL * 32];   // 2 x 4608 B

    int tid = threadIdx.x;
    int wid = tid >> 5, lane = tid & 31;
    int m0 = blockIdx.x * 64 + wid * 16;
    int r0 = m0 + (lane >> 2);
    int kc = (lane & 3) * 2;

    const float* a0p = Wdk + (size_t)r0 * KDK + kc;          // row r0
    const size_t row8 = (size_t)8 * KDK;                     // to row r0+8

    float acc[NTIL][4];
#pragma unroll
    for (int nt = 0; nt < NTIL; nt++)
#pragma unroll
        for (int q = 0; q < 4; q++) acc[nt][q] = 0.f;

    float2 pa[2][4];
    // preload A s=0
    pa[0][0] = *(const float2*)(a0p);
    pa[0][1] = *(const float2*)(a0p + row8);
    pa[0][2] = *(const float2*)(a0p + 8);
    pa[0][3] = *(const float2*)(a0p + row8 + 8);
    // stage B s=0 into Bs[0]
    {
        uint4 t0 = g_Bfrag[tid];
        uint4 t1 = g_Bfrag[tid + 128];
        Bs[0][tid] = t0;
        Bs[0][tid + 128] = t1;
        if (tid < 32) Bs[0][tid + 256] = g_Bfrag[tid + 256];
    }
    __syncthreads();

    for (int s = 0; s < NSTEP; s++) {
        int cb = s & 1, nb = cb ^ 1;
        uint4 t0, t1, t2;
        bool more = (s + 1 < NSTEP);
        if (more) {
            // issue next-step loads early (latency overlapped by MMAs below)
            const uint4* bp = g_Bfrag + (size_t)(s + 1) * (NTIL * 32);
            t0 = bp[tid];
            t1 = bp[tid + 128];
            if (tid < 32) t2 = bp[tid + 256];
            const float* ap = a0p + (size_t)(s + 1) * 16;
            pa[nb][0] = *(const float2*)(ap);
            pa[nb][1] = *(const float2*)(ap + row8);
            pa[nb][2] = *(const float2*)(ap + 8);
            pa[nb][3] = *(const float2*)(ap + row8 + 8);
        }
        // convert A to bf16 hi/lo fragments
        uint32_t ahi[4], alo[4];
#pragma unroll
        for (int q = 0; q < 4; q++) {
            float2 f = pa[cb][q];
            __nv_bfloat162 h = __floats2bfloat162_rn(f.x, f.y);
            ahi[q] = bf2u(h);
            float lx = f.x - __low2float(h);
            float ly = f.y - __high2float(h);
            alo[q] = bf2u(__floats2bfloat162_rn(lx, ly));
        }
        // MMAs, B from smem (broadcast-free, 29-cyc LDS)
#pragma unroll
        for (int nt = 0; nt < NTIL; nt++) {
            uint4 b = Bs[cb][nt * 32 + lane];
            mma16816(acc[nt], ahi, b.x, b.y);   // hi * hi
            mma16816(acc[nt], ahi, b.z, b.w);   // hi * lo
            mma16816(acc[nt], alo, b.x, b.y);   // lo * hi
        }
        // store next B (after MMAs so the LDG latency was covered)
        if (more) {
            Bs[nb][tid] = t0;
            Bs[nb][tid + 128] = t1;
            if (tid < 32) Bs[nb][tid + 256] = t2;
        }
        __syncthreads();
    }

    // epilogue: c0,c1 -> (r0, col, col+1); c2,c3 -> (r0+8, col, col+1)
    int o0 = r0, o1 = r0 + 8;
    float bv0 = bdk[o0], bv1 = bdk[o1];
    int co0 = o0 >> 6, ci0 = o0 & 63;
    int co1 = o1 >> 6, ci1 = o1 & 63;
#pragma unroll
    for (int nt = 0; nt < NTIL; nt++) {
        int colb = nt * 8 + kc;
#pragma unroll
        for (int d = 0; d < 2; d++) {
            int col = colb + d;
            int n = col / 9, j = col % 9;
            g_dwT[((size_t)((n * CPG + ci0) * 9 + j)) * COUT + co0] = acc[nt][d] + bv0;
            g_dwT[((size_t)((n * CPG + ci1) * 9 + j)) * COUT + co1] = acc[nt][2 + d] + bv1;
        }
    }
}

// ---------------- K3: fused depthwise+pointwise (unchanged, proven) ----------------
#define IN_OFF   (CPG * 4 * WW)
#define BUFSZ    816
#define PW_OFF   (IN_OFF + 2 * BUFSZ)
#define SMEM_CONV ((PW_OFF + CPG * CPG) * 4)

__device__ __forceinline__ int refl(int i) {
    return i < 0 ? -i : (i > 63 ? 126 - i : i);
}

__global__ void __launch_bounds__(256, 2) k_conv(const float* __restrict__ pred, float* __restrict__ out) {
    extern __shared__ __align__(16) float sm[];
    float* depth_s = sm;
    float* in_base = sm + IN_OFF;
    float* pw_s    = sm + PW_OFF;

    int tid = threadIdx.x;
    int co = tid & 63;
    int hl = tid >> 6;
    int rb = blockIdx.x, g = blockIdx.y, n = blockIdx.z;
    int h0 = rb * 4;

    const float* base = pred + (size_t)(n * CIN + g * CPG) * HWSZ;

    for (int i = tid; i < CPG * CPG; i += 256) {
        int cm = i >> 6, c = i & 63;
        pw_s[i] = g_pwkn[(size_t)n * ODK + (g * CPG + c) * CPG + cm];
    }

    int i0 = tid, i1 = tid + 256;
    int r0 = i0 / 66, c0p = i0 % 66;
    int r1 = i1 / 66, c1p = i1 % 66;
    bool v1 = (i1 < 396);
    int goff0 = refl(h0 + r0 - 1) * WW + refl(c0p - 1);
    int goff1 = v1 ? (refl(h0 + r1 - 1) * WW + refl(c1p - 1)) : 0;
    int s0 = r0 * 68 + c0p;
    int s1 = r1 * 68 + c1p;

    float q0 = base[goff0];
    float q1 = v1 ? base[goff1] : 0.f;
    const float* wp = g_dwT + ((size_t)(n * CPG) * 9) * COUT + (g * CPG + co);
    float dcur[9], dnxt[9];
#pragma unroll
    for (int k = 0; k < 9; k++) dcur[k] = wp[k * COUT];

    ull acc2[32];
#pragma unroll
    for (int i = 0; i < 32; i++) acc2[i] = 0ULL;

    for (int ci = 0; ci < CPG; ci++) {
        float* ia = in_base + (ci & 1) * BUFSZ;
        float* ib = ia + 408;
        ia[s0] = q0;
        if (c0p) ib[s0 - 1] = q0;
        if (v1) {
            ia[s1] = q1;
            if (c1p) ib[s1 - 1] = q1;
        }
        __syncthreads();

        if (ci + 1 < CPG) {
            const float* pl = base + (size_t)(ci + 1) * HWSZ;
            q0 = pl[goff0];
            q1 = v1 ? pl[goff1] : 0.f;
            const float* wn = wp + (size_t)(ci + 1) * 9 * COUT;
#pragma unroll
            for (int k = 0; k < 9; k++) dnxt[k] = wn[k * COUT];
        }

#pragma unroll
        for (int kh = 0; kh < 3; kh++) {
            const float* row  = &ia[(hl + kh) * 68];
            const float* rowB = row + 408;
            ull w0 = pk2(dcur[kh * 3 + 0], dcur[kh * 3 + 0]);
            ull w1 = pk2(dcur[kh * 3 + 1], dcur[kh * 3 + 1]);
            ull w2 = pk2(dcur[kh * 3 + 2], dcur[kh * 3 + 2]);
#pragma unroll
            for (int c0 = 0; c0 < 64; c0 += 16) {
                const ull* ra = (const ull*)(row + c0);
                ulonglong2 a01 = *(const ulonglong2*)(ra);
                ulonglong2 a23 = *(const ulonglong2*)(ra + 2);
                ulonglong2 a45 = *(const ulonglong2*)(ra + 4);
                ulonglong2 a67 = *(const ulonglong2*)(ra + 6);
                ull a8 = ra[8];
                const ull* rbp = (const ull*)(rowB + c0);
                ulonglong2 b01 = *(const ulonglong2*)(rbp);
                ulonglong2 b23 = *(const ulonglong2*)(rbp + 2);
                ulonglong2 b45 = *(const ulonglong2*)(rbp + 4);
                ulonglong2 b67 = *(const ulonglong2*)(rbp + 6);
                int p = c0 >> 1;
                fma2(acc2[p + 0], w0, a01.x); fma2(acc2[p + 0], w1, b01.x); fma2(acc2[p + 0], w2, a01.y);
                fma2(acc2[p + 1], w0, a01.y); fma2(acc2[p + 1], w1, b01.y); fma2(acc2[p + 1], w2, a23.x);
                fma2(acc2[p + 2], w0, a23.x); fma2(acc2[p + 2], w1, b23.x); fma2(acc2[p + 2], w2, a23.y);
                fma2(acc2[p + 3], w0, a23.y); fma2(acc2[p + 3], w1, b23.y); fma2(acc2[p + 3], w2, a45.x);
                fma2(acc2[p + 4], w0, a45.x); fma2(acc2[p + 4], w1, b45.x); fma2(acc2[p + 4], w2, a45.y);
                fma2(acc2[p + 5], w0, a45.y); fma2(acc2[p + 5], w1, b45.y); fma2(acc2[p + 5], w2, a67.x);
                fma2(acc2[p + 6], w0, a67.x); fma2(acc2[p + 6], w1, b67.x); fma2(acc2[p + 6], w2, a67.y);
                fma2(acc2[p + 7], w0, a67.y); fma2(acc2[p + 7], w1, b67.y); fma2(acc2[p + 7], w2, a8);
            }
        }
#pragma unroll
        for (int k = 0; k < 9; k++) dcur[k] = dnxt[k];
    }

    __syncthreads();
    {
        ull* dst = (ull*)(depth_s + (co * 4 + hl) * 64);
#pragma unroll
        for (int i = 0; i < 32; i++) dst[i] = acc2[i];
    }
    __syncthreads();

#pragma unroll
    for (int i = 0; i < 32; i++) acc2[i] = 0ULL;
    for (int cm = 0; cm < CPG; cm++) {
        float v = pw_s[cm * 64 + co];
        ull vp = pk2(v, v);
        const ulonglong2* ds = (const ulonglong2*)(depth_s + (cm * 4 + hl) * 64);
#pragma unroll
        for (int i = 0; i < 16; i++) {
            ulonglong2 t = ds[i];
            fma2(acc2[2 * i],     vp, t.x);
            fma2(acc2[2 * i + 1], vp, t.y);
        }
    }

    float bias = g_pwbias[n * COUT + g * CPG + co];
    float* op = out + (((size_t)(n * COUT + g * CPG + co)) * HH + (h0 + hl)) * WW;
#pragma unroll
    for (int i = 0; i < 16; i++) {
        float x0, x1, x2, x3;
        upk2(acc2[2 * i], x0, x1);
        upk2(acc2[2 * i + 1], x2, x3);
        *(float4*)(op + 4 * i) = make_float4(x0 + bias, x1 + bias, x2 + bias, x3 + bias);
    }
}

// ---------------- Launch ----------------
extern "C" void kernel_launch(void* const* d_in, const int* in_sizes, int n_in,
                              void* d_out, int out_size) {
    const float* style = (const float*)d_in[0];
    const float* pred  = (const float*)d_in[1];
    const float* Wdk   = (const float*)d_in[2];
    const float* bdk   = (const float*)d_in[3];
    const float* Wpwk  = (const float*)d_in[4];
    const float* bpwk  = (const float*)d_in[5];
    const float* Wpwb  = (const float*)d_in[6];
    const float* bpwb  = (const float*)d_in[7];
    float* out = (float*)d_out;

    cudaFuncSetAttribute(k_conv, cudaFuncAttributeMaxDynamicSharedMemorySize, SMEM_CONV);

    k_pool<<<(NB * SD + 255) / 256, 256>>>(style);
    k_buildB<<<(NSTEP * NTIL * 32 + 255) / 256, 256>>>(style);
    k_pw<<<(ODK + COUT + 255) / 256, 256>>>(Wpwk, bpwk, Wpwb, bpwb);
    k_dk<<<ODK / 64, 128>>>(Wdk, bdk);
    k_conv<<<dim3(HH / 4, NG, NB), 256, SMEM_CONV>>>(pred, out);
}

// round 12
// speedup vs baseline: 1.3579x; 1.0058x over previous
#include <cuda_runtime.h>
#include <cuda_bf16.h>
#include <cstdint>

// ---------------- Problem constants ----------------
#define NB    8
#define SD    512
#define CIN   512
#define COUT  512
#define CPG   64
#define NG    8
#define HH    64
#define WW    64
#define HWSZ  4096
#define KDK   4608
#define ODK   32768
#define NCOL  72
#define NSTEP 288          // KDK / 16
#define HSTEP 144          // NSTEP / 2 (K-split)
#define NTIL  9            // 72 / 8

typedef unsigned long long ull;

// ---------------- Device scratch ----------------
__device__ float g_pooled[NB * SD];
__device__ float g_pwkn[NB * ODK];
__device__ float g_pwbias[NB * COUT];
__device__ __align__(16) uint4 g_Bfrag[NSTEP * NTIL * 32];   // 1.33 MB: {bhi0,bhi1,blo0,blo1} per lane
__device__ float g_dwT[NB * CPG * 9 * COUT];                 // K-half 0 partial (+bias)
__device__ float g_dwT2[NB * CPG * 9 * COUT];                // K-half 1 partial

// ---------------- f32x2 helpers (k_conv) ----------------
__device__ __forceinline__ ull pk2(float lo, float hi) {
    ull r;
    asm("mov.b64 %0, {%1, %2};" : "=l"(r) : "f"(lo), "f"(hi));
    return r;
}
__device__ __forceinline__ void upk2(ull v, float& lo, float& hi) {
    asm("mov.b64 {%0, %1}, %2;" : "=f"(lo), "=f"(hi) : "l"(v));
}
__device__ __forceinline__ void fma2(ull& d, ull a, ull b) {
    asm("fma.rn.f32x2 %0, %1, %2, %0;" : "+l"(d) : "l"(a), "l"(b));
}

// ---------------- mma.sync helper ----------------
__device__ __forceinline__ void mma16816(float* c, const uint32_t* a, uint32_t b0, uint32_t b1) {
    asm volatile(
        "mma.sync.aligned.m16n8k16.row.col.f32.bf16.bf16.f32 "
        "{%0,%1,%2,%3}, {%4,%5,%6,%7}, {%8,%9}, {%0,%1,%2,%3};"
        : "+f"(c[0]), "+f"(c[1]), "+f"(c[2]), "+f"(c[3])
        : "r"(a[0]), "r"(a[1]), "r"(a[2]), "r"(a[3]), "r"(b0), "r"(b1));
}
__device__ __forceinline__ uint32_t bf2u(__nv_bfloat162 h) {
    return *(const uint32_t*)&h;
}

// ---------------- K0: 3x3 avg pool ----------------
__global__ void k_pool(const float* __restrict__ style) {
    int i = blockIdx.x * blockDim.x + threadIdx.x;
    if (i >= NB * SD) return;
    const float* p = style + (size_t)i * 25;
    float s = 0.f;
#pragma unroll
    for (int y = 0; y < 3; y++)
#pragma unroll
        for (int x = 0; x < 3; x++)
            s += p[y * 5 + x];
    g_pooled[i] = s * (1.0f / 9.0f);
}

// ---------------- K0b: build B fragments (mma m16n8k16 col-major layout) ----------------
__device__ __forceinline__ float bval(const float* style, int n, int k) {
    int batch = n / 9, q = n % 9;
    int y = q / 3, x = q % 3;
    int sc = k / 9, rr = k % 9;
    int dy = rr / 3, dx = rr % 3;
    return style[((size_t)(batch * SD + sc) * 5 + (y + dy)) * 5 + (x + dx)];
}

__global__ void k_buildB(const float* __restrict__ style) {
    int i = blockIdx.x * blockDim.x + threadIdx.x;
    if (i >= NSTEP * NTIL * 32) return;
    int lane = i & 31;
    int t = i >> 5;
    int nt = t % NTIL;
    int s = t / NTIL;
    int n = nt * 8 + (lane >> 2);          // n <= 71 always
    int kb = s * 16 + (lane & 3) * 2;
    int kk[4] = {kb, kb + 1, kb + 8, kb + 9};
    float v[4];
#pragma unroll
    for (int q = 0; q < 4; q++) v[q] = bval(style, n, kk[q]);
    __nv_bfloat16 h[4];
    float l[4];
#pragma unroll
    for (int q = 0; q < 4; q++) {
        h[q] = __float2bfloat16(v[q]);
        l[q] = v[q] - __bfloat162float(h[q]);
    }
    uint4 out;
    out.x = bf2u(__nv_bfloat162(h[0], h[1]));
    out.y = bf2u(__nv_bfloat162(h[2], h[3]));
    out.z = bf2u(__floats2bfloat162_rn(l[0], l[1]));
    out.w = bf2u(__floats2bfloat162_rn(l[2], l[3]));
    g_Bfrag[t * 32 + lane] = out;
}

// ---------------- K1: pooled GEMVs ----------------
__global__ void __launch_bounds__(256) k_pw(const float* __restrict__ Wpwk, const float* __restrict__ bpwk,
                                            const float* __restrict__ Wpwb, const float* __restrict__ bpwb) {
    __shared__ float ps[NB * SD];
    int tid = threadIdx.x;
    for (int i = tid; i < NB * SD; i += 256) ps[i] = g_pooled[i];
    __syncthreads();

    int r = blockIdx.x * 256 + tid;
    if (r >= ODK + COUT) return;
    bool isk = (r < ODK);
    int rr = isk ? r : (r - ODK);
    const float* w = isk ? (Wpwk + (size_t)r * SD) : (Wpwb + (size_t)rr * SD);
    float bias = isk ? bpwk[r] : bpwb[rr];

    float acc[NB];
#pragma unroll
    for (int n = 0; n < NB; n++) acc[n] = 0.f;

    for (int s = 0; s < SD; s += 4) {
        float4 wv = *(const float4*)(w + s);
#pragma unroll
        for (int n = 0; n < NB; n++) {
            const float* pp = &ps[n * SD + s];
            acc[n] += wv.x * pp[0] + wv.y * pp[1] + wv.z * pp[2] + wv.w * pp[3];
        }
    }
    if (isk) {
#pragma unroll
        for (int n = 0; n < NB; n++) g_pwkn[(size_t)n * ODK + r] = acc[n] + bias;
    } else {
#pragma unroll
        for (int n = 0; n < NB; n++) g_pwbias[n * COUT + rr] = acc[n] + bias;
    }
}

// ---------------- K2: dk GEMM via mma.sync bf16-split, K-split x2 ----------------
// Grid 1024 = 512 M-blocks x 2 K-halves. 128 threads = 4 warps x 16 rows.
// Half 0 -> g_dwT (+bias); half 1 -> g_dwT2. k_conv sums them.
__global__ void __launch_bounds__(128) k_dk(const float* __restrict__ Wdk, const float* __restrict__ bdk) {
    __shared__ __align__(16) uint4 Bs[2][NTIL * 32];   // 2 x 4608 B

    int tid = threadIdx.x;
    int wid = tid >> 5, lane = tid & 31;
    int bx = blockIdx.x;
    int khalf = bx & 1;
    int mb = bx >> 1;
    int m0 = mb * 64 + wid * 16;
    int r0 = m0 + (lane >> 2);
    int kc = (lane & 3) * 2;
    int sbase = khalf * HSTEP;

    const float* a0p = Wdk + (size_t)r0 * KDK + kc + (size_t)sbase * 16;
    const size_t row8 = (size_t)8 * KDK;
    const uint4* bfrag0 = g_Bfrag + (size_t)sbase * (NTIL * 32);

    float acc[NTIL][4];
#pragma unroll
    for (int nt = 0; nt < NTIL; nt++)
#pragma unroll
        for (int q = 0; q < 4; q++) acc[nt][q] = 0.f;

    float2 pa[2][4];
    // preload A s=0
    pa[0][0] = *(const float2*)(a0p);
    pa[0][1] = *(const float2*)(a0p + row8);
    pa[0][2] = *(const float2*)(a0p + 8);
    pa[0][3] = *(const float2*)(a0p + row8 + 8);
    // stage B s=0 into Bs[0]
    {
        Bs[0][tid] = bfrag0[tid];
        Bs[0][tid + 128] = bfrag0[tid + 128];
        if (tid < 32) Bs[0][tid + 256] = bfrag0[tid + 256];
    }
    __syncthreads();

    for (int s = 0; s < HSTEP; s++) {
        int cb = s & 1, nb = cb ^ 1;
        uint4 t0, t1, t2;
        bool more = (s + 1 < HSTEP);
        if (more) {
            const uint4* bp = bfrag0 + (size_t)(s + 1) * (NTIL * 32);
            t0 = bp[tid];
            t1 = bp[tid + 128];
            if (tid < 32) t2 = bp[tid + 256];
            const float* ap = a0p + (size_t)(s + 1) * 16;
            pa[nb][0] = *(const float2*)(ap);
            pa[nb][1] = *(const float2*)(ap + row8);
            pa[nb][2] = *(const float2*)(ap + 8);
            pa[nb][3] = *(const float2*)(ap + row8 + 8);
        }
        // convert A to bf16 hi/lo fragments
        uint32_t ahi[4], alo[4];
#pragma unroll
        for (int q = 0; q < 4; q++) {
            float2 f = pa[cb][q];
            __nv_bfloat162 h = __floats2bfloat162_rn(f.x, f.y);
            ahi[q] = bf2u(h);
            float lx = f.x - __low2float(h);
            float ly = f.y - __high2float(h);
            alo[q] = bf2u(__floats2bfloat162_rn(lx, ly));
        }
#pragma unroll
        for (int nt = 0; nt < NTIL; nt++) {
            uint4 b = Bs[cb][nt * 32 + lane];
            mma16816(acc[nt], ahi, b.x, b.y);   // hi * hi
            mma16816(acc[nt], ahi, b.z, b.w);   // hi * lo
            mma16816(acc[nt], alo, b.x, b.y);   // lo * hi
        }
        if (more) {
            Bs[nb][tid] = t0;
            Bs[nb][tid + 128] = t1;
            if (tid < 32) Bs[nb][tid + 256] = t2;
        }
        __syncthreads();
    }

    // epilogue
    int o0 = r0, o1 = r0 + 8;
    float bv0 = (khalf == 0) ? bdk[o0] : 0.f;
    float bv1 = (khalf == 0) ? bdk[o1] : 0.f;
    float* dst = (khalf == 0) ? g_dwT : g_dwT2;
    int co0 = o0 >> 6, ci0 = o0 & 63;
    int co1 = o1 >> 6, ci1 = o1 & 63;
#pragma unroll
    for (int nt = 0; nt < NTIL; nt++) {
        int colb = nt * 8 + kc;
#pragma unroll
        for (int d = 0; d < 2; d++) {
            int col = colb + d;
            int n = col / 9, j = col % 9;
            dst[((size_t)((n * CPG + ci0) * 9 + j)) * COUT + co0] = acc[nt][d] + bv0;
            dst[((size_t)((n * CPG + ci1) * 9 + j)) * COUT + co1] = acc[nt][2 + d] + bv1;
        }
    }
}

// ---------------- K3: fused depthwise+pointwise ----------------
#define IN_OFF   (CPG * 4 * WW)
#define BUFSZ    816
#define PW_OFF   (IN_OFF + 2 * BUFSZ)
#define SMEM_CONV ((PW_OFF + CPG * CPG) * 4)

__device__ __forceinline__ int refl(int i) {
    return i < 0 ? -i : (i > 63 ? 126 - i : i);
}

__global__ void __launch_bounds__(256, 2) k_conv(const float* __restrict__ pred, float* __restrict__ out) {
    extern __shared__ __align__(16) float sm[];
    float* depth_s = sm;
    float* in_base = sm + IN_OFF;
    float* pw_s    = sm + PW_OFF;

    int tid = threadIdx.x;
    int co = tid & 63;
    int hl = tid >> 6;
    int rb = blockIdx.x, g = blockIdx.y, n = blockIdx.z;
    int h0 = rb * 4;

    const float* base = pred + (size_t)(n * CIN + g * CPG) * HWSZ;

    for (int i = tid; i < CPG * CPG; i += 256) {
        int cm = i >> 6, c = i & 63;
        pw_s[i] = g_pwkn[(size_t)n * ODK + (g * CPG + c) * CPG + cm];
    }

    int i0 = tid, i1 = tid + 256;
    int r0 = i0 / 66, c0p = i0 % 66;
    int r1 = i1 / 66, c1p = i1 % 66;
    bool v1 = (i1 < 396);
    int goff0 = refl(h0 + r0 - 1) * WW + refl(c0p - 1);
    int goff1 = v1 ? (refl(h0 + r1 - 1) * WW + refl(c1p - 1)) : 0;
    int s0 = r0 * 68 + c0p;
    int s1 = r1 * 68 + c1p;

    float q0 = base[goff0];
    float q1 = v1 ? base[goff1] : 0.f;
    size_t woff = ((size_t)(n * CPG) * 9) * COUT + (g * CPG + co);
    const float* wp  = g_dwT  + woff;
    const float* wp2 = g_dwT2 + woff;
    float dcur[9], dnxt[9];
#pragma unroll
    for (int k = 0; k < 9; k++) dcur[k] = wp[k * COUT] + wp2[k * COUT];

    ull acc2[32];
#pragma unroll
    for (int i = 0; i < 32; i++) acc2[i] = 0ULL;

    for (int ci = 0; ci < CPG; ci++) {
        float* ia = in_base + (ci & 1) * BUFSZ;
        float* ib = ia + 408;
        ia[s0] = q0;
        if (c0p) ib[s0 - 1] = q0;
        if (v1) {
            ia[s1] = q1;
            if (c1p) ib[s1 - 1] = q1;
        }
        __syncthreads();

        if (ci + 1 < CPG) {
            const float* pl = base + (size_t)(ci + 1) * HWSZ;
            q0 = pl[goff0];
            q1 = v1 ? pl[goff1] : 0.f;
            const float* wn  = wp  + (size_t)(ci + 1) * 9 * COUT;
            const float* wn2 = wp2 + (size_t)(ci + 1) * 9 * COUT;
#pragma unroll
            for (int k = 0; k < 9; k++) dnxt[k] = wn[k * COUT] + wn2[k * COUT];
        }

#pragma unroll
        for (int kh = 0; kh < 3; kh++) {
            const float* row  = &ia[(hl + kh) * 68];
            const float* rowB = row + 408;
            ull w0 = pk2(dcur[kh * 3 + 0], dcur[kh * 3 + 0]);
            ull w1 = pk2(dcur[kh * 3 + 1], dcur[kh * 3 + 1]);
            ull w2 = pk2(dcur[kh * 3 + 2], dcur[kh * 3 + 2]);
#pragma unroll
            for (int c0 = 0; c0 < 64; c0 += 16) {
                const ull* ra = (const ull*)(row + c0);
                ulonglong2 a01 = *(const ulonglong2*)(ra);
                ulonglong2 a23 = *(const ulonglong2*)(ra + 2);
                ulonglong2 a45 = *(const ulonglong2*)(ra + 4);
                ulonglong2 a67 = *(const ulonglong2*)(ra + 6);
                ull a8 = ra[8];
                const ull* rbp = (const ull*)(rowB + c0);
                ulonglong2 b01 = *(const ulonglong2*)(rbp);
                ulonglong2 b23 = *(const ulonglong2*)(rbp + 2);
                ulonglong2 b45 = *(const ulonglong2*)(rbp + 4);
                ulonglong2 b67 = *(const ulonglong2*)(rbp + 6);
                int p = c0 >> 1;
                fma2(acc2[p + 0], w0, a01.x); fma2(acc2[p + 0], w1, b01.x); fma2(acc2[p + 0], w2, a01.y);
                fma2(acc2[p + 1], w0, a01.y); fma2(acc2[p + 1], w1, b01.y); fma2(acc2[p + 1], w2, a23.x);
                fma2(acc2[p + 2], w0, a23.x); fma2(acc2[p + 2], w1, b23.x); fma2(acc2[p + 2], w2, a23.y);
                fma2(acc2[p + 3], w0, a23.y); fma2(acc2[p + 3], w1, b23.y); fma2(acc2[p + 3], w2, a45.x);
                fma2(acc2[p + 4], w0, a45.x); fma2(acc2[p + 4], w1, b45.x); fma2(acc2[p + 4], w2, a45.y);
                fma2(acc2[p + 5], w0, a45.y); fma2(acc2[p + 5], w1, b45.y); fma2(acc2[p + 5], w2, a67.x);
                fma2(acc2[p + 6], w0, a67.x); fma2(acc2[p + 6], w1, b67.x); fma2(acc2[p + 6], w2, a67.y);
                fma2(acc2[p + 7], w0, a67.y); fma2(acc2[p + 7], w1, b67.y); fma2(acc2[p + 7], w2, a8);
            }
        }
#pragma unroll
        for (int k = 0; k < 9; k++) dcur[k] = dnxt[k];
    }

    __syncthreads();
    {
        ull* dst = (ull*)(depth_s + (co * 4 + hl) * 64);
#pragma unroll
        for (int i = 0; i < 32; i++) dst[i] = acc2[i];
    }
    __syncthreads();

#pragma unroll
    for (int i = 0; i < 32; i++) acc2[i] = 0ULL;
    for (int cm = 0; cm < CPG; cm++) {
        float v = pw_s[cm * 64 + co];
        ull vp = pk2(v, v);
        const ulonglong2* ds = (const ulonglong2*)(depth_s + (cm * 4 + hl) * 64);
#pragma unroll
        for (int i = 0; i < 16; i++) {
            ulonglong2 t = ds[i];
            fma2(acc2[2 * i],     vp, t.x);
            fma2(acc2[2 * i + 1], vp, t.y);
        }
    }

    float bias = g_pwbias[n * COUT + g * CPG + co];
    float* op = out + (((size_t)(n * COUT + g * CPG + co)) * HH + (h0 + hl)) * WW;
#pragma unroll
    for (int i = 0; i < 16; i++) {
        float x0, x1, x2, x3;
        upk2(acc2[2 * i], x0, x1);
        upk2(acc2[2 * i + 1], x2, x3);
        *(float4*)(op + 4 * i) = make_float4(x0 + bias, x1 + bias, x2 + bias, x3 + bias);
    }
}

// ---------------- Launch ----------------
extern "C" void kernel_launch(void* const* d_in, const int* in_sizes, int n_in,
                              void* d_out, int out_size) {
    const float* style = (const float*)d_in[0];
    const float* pred  = (const float*)d_in[1];
    const float* Wdk   = (const float*)d_in[2];
    const float* bdk   = (const float*)d_in[3];
    const float* Wpwk  = (const float*)d_in[4];
    const float* bpwk  = (const float*)d_in[5];
    const float* Wpwb  = (const float*)d_in[6];
    const float* bpwb  = (const float*)d_in[7];
    float* out = (float*)d_out;

    cudaFuncSetAttribute(k_conv, cudaFuncAttributeMaxDynamicSharedMemorySize, SMEM_CONV);

    k_pool<<<(NB * SD + 255) / 256, 256>>>(style);
    k_buildB<<<(NSTEP * NTIL * 32 + 255) / 256, 256>>>(style);
    k_pw<<<(ODK + COUT + 255) / 256, 256>>>(Wpwk, bpwk, Wpwb, bpwb);
    k_dk<<<1024, 128>>>(Wdk, bdk);
    k_conv<<<dim3(HH / 4, NG, NB), 256, SMEM_CONV>>>(pred, out);
}

// round 13
// speedup vs baseline: 1.3620x; 1.0030x over previous
#include <cuda_runtime.h>
#include <cuda_bf16.h>
#include <cstdint>

// ---------------- Problem constants ----------------
#define NB    8
#define SD    512
#define CIN   512
#define COUT  512
#define CPG   64
#define NG    8
#define HH    64
#define WW    64
#define HWSZ  4096
#define KDK   4608
#define ODK   32768
#define NCOL  72
#define NSTEP 288          // KDK / 16
#define HSTEP 144          // NSTEP / 2 (K-split)
#define NTIL  9            // 72 / 8
#define BSTG  (NTIL * 32)  // 288 uint4 per B stage

typedef unsigned long long ull;

// ---------------- Device scratch ----------------
__device__ float g_pooled[NB * SD];
__device__ float g_pwkn[NB * ODK];
__device__ float g_pwbias[NB * COUT];
__device__ __align__(16) uint4 g_Bfrag[NSTEP * NTIL * 32];   // 1.33 MB: {bhi0,bhi1,blo0,blo1} per lane
__device__ float g_dwT[NB * CPG * 9 * COUT];                 // K-half 0 partial (+bias)
__device__ float g_dwT2[NB * CPG * 9 * COUT];                // K-half 1 partial

// ---------------- f32x2 helpers (k_conv) ----------------
__device__ __forceinline__ ull pk2(float lo, float hi) {
    ull r;
    asm("mov.b64 %0, {%1, %2};" : "=l"(r) : "f"(lo), "f"(hi));
    return r;
}
__device__ __forceinline__ void upk2(ull v, float& lo, float& hi) {
    asm("mov.b64 {%0, %1}, %2;" : "=f"(lo), "=f"(hi) : "l"(v));
}
__device__ __forceinline__ void fma2(ull& d, ull a, ull b) {
    asm("fma.rn.f32x2 %0, %1, %2, %0;" : "+l"(d) : "l"(a), "l"(b));
}

// ---------------- mma.sync / cp.async helpers ----------------
__device__ __forceinline__ void mma16816(float* c, const uint32_t* a, uint32_t b0, uint32_t b1) {
    asm volatile(
        "mma.sync.aligned.m16n8k16.row.col.f32.bf16.bf16.f32 "
        "{%0,%1,%2,%3}, {%4,%5,%6,%7}, {%8,%9}, {%0,%1,%2,%3};"
        : "+f"(c[0]), "+f"(c[1]), "+f"(c[2]), "+f"(c[3])
        : "r"(a[0]), "r"(a[1]), "r"(a[2]), "r"(a[3]), "r"(b0), "r"(b1));
}
__device__ __forceinline__ uint32_t bf2u(__nv_bfloat162 h) {
    return *(const uint32_t*)&h;
}
__device__ __forceinline__ void cp16(uint32_t saddr, const void* gaddr) {
    asm volatile("cp.async.cg.shared.global [%0], [%1], 16;" :: "r"(saddr), "l"(gaddr));
}
#define CP_COMMIT() asm volatile("cp.async.commit_group;" ::: "memory")
#define CP_WAIT1()  asm volatile("cp.async.wait_group 1;" ::: "memory")

// ---------------- K0: 3x3 avg pool ----------------
__global__ void k_pool(const float* __restrict__ style) {
    int i = blockIdx.x * blockDim.x + threadIdx.x;
    if (i >= NB * SD) return;
    const float* p = style + (size_t)i * 25;
    float s = 0.f;
#pragma unroll
    for (int y = 0; y < 3; y++)
#pragma unroll
        for (int x = 0; x < 3; x++)
            s += p[y * 5 + x];
    g_pooled[i] = s * (1.0f / 9.0f);
}

// ---------------- K0b: build B fragments (mma m16n8k16 col-major layout) ----------------
__device__ __forceinline__ float bval(const float* style, int n, int k) {
    int batch = n / 9, q = n % 9;
    int y = q / 3, x = q % 3;
    int sc = k / 9, rr = k % 9;
    int dy = rr / 3, dx = rr % 3;
    return style[((size_t)(batch * SD + sc) * 5 + (y + dy)) * 5 + (x + dx)];
}

__global__ void k_buildB(const float* __restrict__ style) {
    int i = blockIdx.x * blockDim.x + threadIdx.x;
    if (i >= NSTEP * NTIL * 32) return;
    int lane = i & 31;
    int t = i >> 5;
    int nt = t % NTIL;
    int s = t / NTIL;
    int n = nt * 8 + (lane >> 2);
    int kb = s * 16 + (lane & 3) * 2;
    int kk[4] = {kb, kb + 1, kb + 8, kb + 9};
    float v[4];
#pragma unroll
    for (int q = 0; q < 4; q++) v[q] = bval(style, n, kk[q]);
    __nv_bfloat16 h[4];
    float l[4];
#pragma unroll
    for (int q = 0; q < 4; q++) {
        h[q] = __float2bfloat16(v[q]);
        l[q] = v[q] - __bfloat162float(h[q]);
    }
    uint4 out;
    out.x = bf2u(__nv_bfloat162(h[0], h[1]));
    out.y = bf2u(__nv_bfloat162(h[2], h[3]));
    out.z = bf2u(__floats2bfloat162_rn(l[0], l[1]));
    out.w = bf2u(__floats2bfloat162_rn(l[2], l[3]));
    g_Bfrag[t * 32 + lane] = out;
}

// ---------------- K1: pooled GEMVs ----------------
__global__ void __launch_bounds__(256) k_pw(const float* __restrict__ Wpwk, const float* __restrict__ bpwk,
                                            const float* __restrict__ Wpwb, const float* __restrict__ bpwb) {
    __shared__ float ps[NB * SD];
    int tid = threadIdx.x;
    for (int i = tid; i < NB * SD; i += 256) ps[i] = g_pooled[i];
    __syncthreads();

    int r = blockIdx.x * 256 + tid;
    if (r >= ODK + COUT) return;
    bool isk = (r < ODK);
    int rr = isk ? r : (r - ODK);
    const float* w = isk ? (Wpwk + (size_t)r * SD) : (Wpwb + (size_t)rr * SD);
    float bias = isk ? bpwk[r] : bpwb[rr];

    float acc[NB];
#pragma unroll
    for (int n = 0; n < NB; n++) acc[n] = 0.f;

    for (int s = 0; s < SD; s += 4) {
        float4 wv = *(const float4*)(w + s);
#pragma unroll
        for (int n = 0; n < NB; n++) {
            const float* pp = &ps[n * SD + s];
            acc[n] += wv.x * pp[0] + wv.y * pp[1] + wv.z * pp[2] + wv.w * pp[3];
        }
    }
    if (isk) {
#pragma unroll
        for (int n = 0; n < NB; n++) g_pwkn[(size_t)n * ODK + r] = acc[n] + bias;
    } else {
#pragma unroll
        for (int n = 0; n < NB; n++) g_pwbias[n * COUT + rr] = acc[n] + bias;
    }
}

// ---------------- K2: dk GEMM via mma.sync bf16-split, deep pipelines ----------------
// Grid 1024 = 512 M-blocks x 2 K-halves. 128 threads = 4 warps x 16 rows.
// A: 3 register buffers (3 steps ahead). B: 3-stage smem ring via cp.async.
__global__ void __launch_bounds__(128) k_dk(const float* __restrict__ Wdk, const float* __restrict__ bdk) {
    __shared__ __align__(16) uint4 Bs[3][BSTG];   // 3 x 4608 B

    int tid = threadIdx.x;
    int wid = tid >> 5, lane = tid & 31;
    int bx = blockIdx.x;
    int khalf = bx & 1;
    int mb = bx >> 1;
    int m0 = mb * 64 + wid * 16;
    int r0 = m0 + (lane >> 2);
    int kc = (lane & 3) * 2;
    int sbase = khalf * HSTEP;

    const float* a0p = Wdk + (size_t)r0 * KDK + kc + (size_t)sbase * 16;
    const size_t row8 = (size_t)8 * KDK;
    const uint4* bfrag0 = g_Bfrag + (size_t)sbase * BSTG;

    uint32_t bs_addr[3];
#pragma unroll
    for (int b = 0; b < 3; b++) bs_addr[b] = (uint32_t)__cvta_generic_to_shared(&Bs[b][0]);

    float acc[NTIL][4];
#pragma unroll
    for (int nt = 0; nt < NTIL; nt++)
#pragma unroll
        for (int q = 0; q < 4; q++) acc[nt][q] = 0.f;

    // ---- prologue: A steps 0..2 into regs; B stages 0,1 via cp.async ----
    float2 pa[3][4];
#pragma unroll
    for (int d = 0; d < 3; d++) {
        const float* ap = a0p + (size_t)d * 16;
        pa[d][0] = *(const float2*)(ap);
        pa[d][1] = *(const float2*)(ap + row8);
        pa[d][2] = *(const float2*)(ap + 8);
        pa[d][3] = *(const float2*)(ap + row8 + 8);
    }
#pragma unroll
    for (int st = 0; st < 2; st++) {
        const uint4* src = bfrag0 + (size_t)st * BSTG;
        cp16(bs_addr[st] + tid * 16, src + tid);
        cp16(bs_addr[st] + (tid + 128) * 16, src + tid + 128);
        if (tid < 32) cp16(bs_addr[st] + (tid + 256) * 16, src + tid + 256);
        CP_COMMIT();
    }
    CP_WAIT1();           // stage 0 complete
    __syncthreads();

    for (int s = 0; s < HSTEP; s++) {
        int cb = s % 3;
        // convert A(s) to bf16 hi/lo fragments
        uint32_t ahi[4], alo[4];
#pragma unroll
        for (int q = 0; q < 4; q++) {
            float2 f = pa[cb][q];
            __nv_bfloat162 h = __floats2bfloat162_rn(f.x, f.y);
            ahi[q] = bf2u(h);
            float lx = f.x - __low2float(h);
            float ly = f.y - __high2float(h);
            alo[q] = bf2u(__floats2bfloat162_rn(lx, ly));
        }
        // issue A loads for s+3 (reuse buffer cb after convert consumed it)
        if (s + 3 < HSTEP) {
            const float* ap = a0p + (size_t)(s + 3) * 16;
            pa[cb][0] = *(const float2*)(ap);
            pa[cb][1] = *(const float2*)(ap + row8);
            pa[cb][2] = *(const float2*)(ap + 8);
            pa[cb][3] = *(const float2*)(ap + row8 + 8);
        }
        // issue B stage s+2 via cp.async (buffer (s+2)%3 was released at end of s-1)
        if (s + 2 < HSTEP) {
            int nb = (s + 2) % 3;
            const uint4* src = bfrag0 + (size_t)(s + 2) * BSTG;
            cp16(bs_addr[nb] + tid * 16, src + tid);
            cp16(bs_addr[nb] + (tid + 128) * 16, src + tid + 128);
            if (tid < 32) cp16(bs_addr[nb] + (tid + 256) * 16, src + tid + 256);
        }
        CP_COMMIT();      // always commit (possibly empty) to keep group counting aligned
        // MMAs with B(s) from smem
#pragma unroll
        for (int nt = 0; nt < NTIL; nt++) {
            uint4 b = Bs[cb][nt * 32 + lane];
            mma16816(acc[nt], ahi, b.x, b.y);   // hi * hi
            mma16816(acc[nt], ahi, b.z, b.w);   // hi * lo
            mma16816(acc[nt], alo, b.x, b.y);   // lo * hi
        }
        CP_WAIT1();       // stage s+1 complete
        __syncthreads();
    }

    // epilogue
    int o0 = r0, o1 = r0 + 8;
    float bv0 = (khalf == 0) ? bdk[o0] : 0.f;
    float bv1 = (khalf == 0) ? bdk[o1] : 0.f;
    float* dst = (khalf == 0) ? g_dwT : g_dwT2;
    int co0 = o0 >> 6, ci0 = o0 & 63;
    int co1 = o1 >> 6, ci1 = o1 & 63;
#pragma unroll
    for (int nt = 0; nt < NTIL; nt++) {
        int colb = nt * 8 + kc;
#pragma unroll
        for (int d = 0; d < 2; d++) {
            int col = colb + d;
            int n = col / 9, j = col % 9;
            dst[((size_t)((n * CPG + ci0) * 9 + j)) * COUT + co0] = acc[nt][d] + bv0;
            dst[((size_t)((n * CPG + ci1) * 9 + j)) * COUT + co1] = acc[nt][2 + d] + bv1;
        }
    }
}

// ---------------- K3: fused depthwise+pointwise ----------------
#define IN_OFF   (CPG * 4 * WW)
#define BUFSZ    816
#define PW_OFF   (IN_OFF + 2 * BUFSZ)
#define SMEM_CONV ((PW_OFF + CPG * CPG) * 4)

__device__ __forceinline__ int refl(int i) {
    return i < 0 ? -i : (i > 63 ? 126 - i : i);
}

__global__ void __launch_bounds__(256, 2) k_conv(const float* __restrict__ pred, float* __restrict__ out) {
    extern __shared__ __align__(16) float sm[];
    float* depth_s = sm;
    float* in_base = sm + IN_OFF;
    float* pw_s    = sm + PW_OFF;

    int tid = threadIdx.x;
    int co = tid & 63;
    int hl = tid >> 6;
    int rb = blockIdx.x, g = blockIdx.y, n = blockIdx.z;
    int h0 = rb * 4;

    const float* base = pred + (size_t)(n * CIN + g * CPG) * HWSZ;

    for (int i = tid; i < CPG * CPG; i += 256) {
        int cm = i >> 6, c = i & 63;
        pw_s[i] = g_pwkn[(size_t)n * ODK + (g * CPG + c) * CPG + cm];
    }

    int i0 = tid, i1 = tid + 256;
    int r0 = i0 / 66, c0p = i0 % 66;
    int r1 = i1 / 66, c1p = i1 % 66;
    bool v1 = (i1 < 396);
    int goff0 = refl(h0 + r0 - 1) * WW + refl(c0p - 1);
    int goff1 = v1 ? (refl(h0 + r1 - 1) * WW + refl(c1p - 1)) : 0;
    int s0 = r0 * 68 + c0p;
    int s1 = r1 * 68 + c1p;

    float q0 = base[goff0];
    float q1 = v1 ? base[goff1] : 0.f;
    size_t woff = ((size_t)(n * CPG) * 9) * COUT + (g * CPG + co);
    const float* wp  = g_dwT  + woff;
    const float* wp2 = g_dwT2 + woff;
    float dcur[9], dnxt[9];
#pragma unroll
    for (int k = 0; k < 9; k++) dcur[k] = wp[k * COUT] + wp2[k * COUT];

    ull acc2[32];
#pragma unroll
    for (int i = 0; i < 32; i++) acc2[i] = 0ULL;

    for (int ci = 0; ci < CPG; ci++) {
        float* ia = in_base + (ci & 1) * BUFSZ;
        float* ib = ia + 408;
        ia[s0] = q0;
        if (c0p) ib[s0 - 1] = q0;
        if (v1) {
            ia[s1] = q1;
            if (c1p) ib[s1 - 1] = q1;
        }
        __syncthreads();

        if (ci + 1 < CPG) {
            const float* pl = base + (size_t)(ci + 1) * HWSZ;
            q0 = pl[goff0];
            q1 = v1 ? pl[goff1] : 0.f;
            const float* wn  = wp  + (size_t)(ci + 1) * 9 * COUT;
            const float* wn2 = wp2 + (size_t)(ci + 1) * 9 * COUT;
#pragma unroll
            for (int k = 0; k < 9; k++) dnxt[k] = wn[k * COUT] + wn2[k * COUT];
        }

#pragma unroll
        for (int kh = 0; kh < 3; kh++) {
            const float* row  = &ia[(hl + kh) * 68];
            const float* rowB = row + 408;
            ull w0 = pk2(dcur[kh * 3 + 0], dcur[kh * 3 + 0]);
            ull w1 = pk2(dcur[kh * 3 + 1], dcur[kh * 3 + 1]);
            ull w2 = pk2(dcur[kh * 3 + 2], dcur[kh * 3 + 2]);
#pragma unroll
            for (int c0 = 0; c0 < 64; c0 += 16) {
                const ull* ra = (const ull*)(row + c0);
                ulonglong2 a01 = *(const ulonglong2*)(ra);
                ulonglong2 a23 = *(const ulonglong2*)(ra + 2);
                ulonglong2 a45 = *(const ulonglong2*)(ra + 4);
                ulonglong2 a67 = *(const ulonglong2*)(ra + 6);
                ull a8 = ra[8];
                const ull* rbp = (const ull*)(rowB + c0);
                ulonglong2 b01 = *(const ulonglong2*)(rbp);
                ulonglong2 b23 = *(const ulonglong2*)(rbp + 2);
                ulonglong2 b45 = *(const ulonglong2*)(rbp + 4);
                ulonglong2 b67 = *(const ulonglong2*)(rbp + 6);
                int p = c0 >> 1;
                fma2(acc2[p + 0], w0, a01.x); fma2(acc2[p + 0], w1, b01.x); fma2(acc2[p + 0], w2, a01.y);
                fma2(acc2[p + 1], w0, a01.y); fma2(acc2[p + 1], w1, b01.y); fma2(acc2[p + 1], w2, a23.x);
                fma2(acc2[p + 2], w0, a23.x); fma2(acc2[p + 2], w1, b23.x); fma2(acc2[p + 2], w2, a23.y);
                fma2(acc2[p + 3], w0, a23.y); fma2(acc2[p + 3], w1, b23.y); fma2(acc2[p + 3], w2, a45.x);
                fma2(acc2[p + 4], w0, a45.x); fma2(acc2[p + 4], w1, b45.x); fma2(acc2[p + 4], w2, a45.y);
                fma2(acc2[p + 5], w0, a45.y); fma2(acc2[p + 5], w1, b45.y); fma2(acc2[p + 5], w2, a67.x);
                fma2(acc2[p + 6], w0, a67.x); fma2(acc2[p + 6], w1, b67.x); fma2(acc2[p + 6], w2, a67.y);
                fma2(acc2[p + 7], w0, a67.y); fma2(acc2[p + 7], w1, b67.y); fma2(acc2[p + 7], w2, a8);
            }
        }
#pragma unroll
        for (int k = 0; k < 9; k++) dcur[k] = dnxt[k];
    }

    __syncthreads();
    {
        ull* dst = (ull*)(depth_s + (co * 4 + hl) * 64);
#pragma unroll
        for (int i = 0; i < 32; i++) dst[i] = acc2[i];
    }
    __syncthreads();

#pragma unroll
    for (int i = 0; i < 32; i++) acc2[i] = 0ULL;
    for (int cm = 0; cm < CPG; cm++) {
        float v = pw_s[cm * 64 + co];
        ull vp = pk2(v, v);
        const ulonglong2* ds = (const ulonglong2*)(depth_s + (cm * 4 + hl) * 64);
#pragma unroll
        for (int i = 0; i < 16; i++) {
            ulonglong2 t = ds[i];
            fma2(acc2[2 * i],     vp, t.x);
            fma2(acc2[2 * i + 1], vp, t.y);
        }
    }

    float bias = g_pwbias[n * COUT + g * CPG + co];
    float* op = out + (((size_t)(n * COUT + g * CPG + co)) * HH + (h0 + hl)) * WW;
#pragma unroll
    for (int i = 0; i < 16; i++) {
        float x0, x1, x2, x3;
        upk2(acc2[2 * i], x0, x1);
        upk2(acc2[2 * i + 1], x2, x3);
        *(float4*)(op + 4 * i) = make_float4(x0 + bias, x1 + bias, x2 + bias, x3 + bias);
    }
}

// ---------------- Launch ----------------
extern "C" void kernel_launch(void* const* d_in, const int* in_sizes, int n_in,
                              void* d_out, int out_size) {
    const float* style = (const float*)d_in[0];
    const float* pred  = (const float*)d_in[1];
    const float* Wdk   = (const float*)d_in[2];
    const float* bdk   = (const float*)d_in[3];
    const float* Wpwk  = (const float*)d_in[4];
    const float* bpwk  = (const float*)d_in[5];
    const float* Wpwb  = (const float*)d_in[6];
    const float* bpwb  = (const float*)d_in[7];
    float* out = (float*)d_out;

    cudaFuncSetAttribute(k_conv, cudaFuncAttributeMaxDynamicSharedMemorySize, SMEM_CONV);

    k_pool<<<(NB * SD + 255) / 256, 256>>>(style);
    k_buildB<<<(NSTEP * NTIL * 32 + 255) / 256, 256>>>(style);
    k_pw<<<(ODK + COUT + 255) / 256, 256>>>(Wpwk, bpwk, Wpwb, bpwb);
    k_dk<<<1024, 128>>>(Wdk, bdk);
    k_conv<<<dim3(HH / 4, NG, NB), 256, SMEM_CONV>>>(pred, out);
}

// round 14
// speedup vs baseline: 1.4653x; 1.0759x over previous
#include <cuda_runtime.h>
#include <cuda_bf16.h>
#include <cstdint>

// ---------------- Problem constants ----------------
#define NB    8
#define SD    512
#define CIN   512
#define COUT  512
#define CPG   64
#define NG    8
#define HH    64
#define WW    64
#define HWSZ  4096
#define KDK   4608
#define ODK   32768
#define NCOL  72
#define NSTEP 288          // KDK / 16
#define KSPLIT 4
#define QSTEP (NSTEP / KSPLIT)   // 72
#define NTIL  9            // 72 / 8
#define BSTG  (NTIL * 32)  // 288 uint4 per B stage
#define DWSZ  (NB * CPG * 9 * COUT)

typedef unsigned long long ull;

// ---------------- Device scratch ----------------
__device__ float g_pooled[NB * SD];
__device__ float g_pwkn[NB * ODK];
__device__ float g_pwbias[NB * COUT];
__device__ __align__(16) uint4 g_Bfrag[NSTEP * NTIL * 32];   // K-permuted bf16 hi/lo B fragments
__device__ float g_dwP[KSPLIT][DWSZ];                        // K-quarter partials
__device__ float g_dwT[DWSZ];                                // merged depthwise weights [n][ci][k][co]

// ---------------- f32x2 helpers (k_conv) ----------------
__device__ __forceinline__ ull pk2(float lo, float hi) {
    ull r;
    asm("mov.b64 %0, {%1, %2};" : "=l"(r) : "f"(lo), "f"(hi));
    return r;
}
__device__ __forceinline__ void upk2(ull v, float& lo, float& hi) {
    asm("mov.b64 {%0, %1}, %2;" : "=f"(lo), "=f"(hi) : "l"(v));
}
__device__ __forceinline__ void fma2(ull& d, ull a, ull b) {
    asm("fma.rn.f32x2 %0, %1, %2, %0;" : "+l"(d) : "l"(a), "l"(b));
}

// ---------------- mma.sync / cp.async helpers ----------------
__device__ __forceinline__ void mma16816(float* c, const uint32_t* a, uint32_t b0, uint32_t b1) {
    asm volatile(
        "mma.sync.aligned.m16n8k16.row.col.f32.bf16.bf16.f32 "
        "{%0,%1,%2,%3}, {%4,%5,%6,%7}, {%8,%9}, {%0,%1,%2,%3};"
        : "+f"(c[0]), "+f"(c[1]), "+f"(c[2]), "+f"(c[3])
        : "r"(a[0]), "r"(a[1]), "r"(a[2]), "r"(a[3]), "r"(b0), "r"(b1));
}
__device__ __forceinline__ uint32_t bf2u(__nv_bfloat162 h) {
    return *(const uint32_t*)&h;
}
__device__ __forceinline__ void cp16(uint32_t saddr, const void* gaddr) {
    asm volatile("cp.async.cg.shared.global [%0], [%1], 16;" :: "r"(saddr), "l"(gaddr));
}
#define CP_COMMIT() asm volatile("cp.async.commit_group;" ::: "memory")
#define CP_WAIT1()  asm volatile("cp.async.wait_group 1;" ::: "memory")

// ---------------- K0: 3x3 avg pool ----------------
__global__ void k_pool(const float* __restrict__ style) {
    int i = blockIdx.x * blockDim.x + threadIdx.x;
    if (i >= NB * SD) return;
    const float* p = style + (size_t)i * 25;
    float s = 0.f;
#pragma unroll
    for (int y = 0; y < 3; y++)
#pragma unroll
        for (int x = 0; x < 3; x++)
            s += p[y * 5 + x];
    g_pooled[i] = s * (1.0f / 9.0f);
}

// ---------------- K0b: build K-PERMUTED B fragments ----------------
// mma slot-k {2q,2q+1} <- mem k {4q,4q+1}; slot-k {2q+8,2q+9} <- mem k {4q+2,4q+3}.
// A side loads one contiguous float4 per row per k16 step; B built to match.
__device__ __forceinline__ float bval(const float* style, int n, int k) {
    int batch = n / 9, q = n % 9;
    int y = q / 3, x = q % 3;
    int sc = k / 9, rr = k % 9;
    int dy = rr / 3, dx = rr % 3;
    return style[((size_t)(batch * SD + sc) * 5 + (y + dy)) * 5 + (x + dx)];
}

__global__ void k_buildB(const float* __restrict__ style) {
    int i = blockIdx.x * blockDim.x + threadIdx.x;
    if (i >= NSTEP * NTIL * 32) return;
    int lane = i & 31;
    int t = i >> 5;
    int nt = t % NTIL;
    int s = t / NTIL;
    int n = nt * 8 + (lane >> 2);
    int kb = s * 16 + (lane & 3) * 4;          // contiguous 4 mem-k per thread (permuted)
    float v[4];
#pragma unroll
    for (int q = 0; q < 4; q++) v[q] = bval(style, n, kb + q);
    __nv_bfloat16 h[4];
    float l[4];
#pragma unroll
    for (int q = 0; q < 4; q++) {
        h[q] = __float2bfloat16(v[q]);
        l[q] = v[q] - __bfloat162float(h[q]);
    }
    uint4 out;
    out.x = bf2u(__nv_bfloat162(h[0], h[1]));   // slot b0 (k pair 2q)
    out.y = bf2u(__nv_bfloat162(h[2], h[3]));   // slot b1 (k pair 2q+8)
    out.z = bf2u(__floats2bfloat162_rn(l[0], l[1]));
    out.w = bf2u(__floats2bfloat162_rn(l[2], l[3]));
    g_Bfrag[t * 32 + lane] = out;
}

// ---------------- K1: pooled GEMVs ----------------
__global__ void __launch_bounds__(256) k_pw(const float* __restrict__ Wpwk, const float* __restrict__ bpwk,
                                            const float* __restrict__ Wpwb, const float* __restrict__ bpwb) {
    __shared__ float ps[NB * SD];
    int tid = threadIdx.x;
    for (int i = tid; i < NB * SD; i += 256) ps[i] = g_pooled[i];
    __syncthreads();

    int r = blockIdx.x * 256 + tid;
    if (r >= ODK + COUT) return;
    bool isk = (r < ODK);
    int rr = isk ? r : (r - ODK);
    const float* w = isk ? (Wpwk + (size_t)r * SD) : (Wpwb + (size_t)rr * SD);
    float bias = isk ? bpwk[r] : bpwb[rr];

    float acc[NB];
#pragma unroll
    for (int n = 0; n < NB; n++) acc[n] = 0.f;

    for (int s = 0; s < SD; s += 4) {
        float4 wv = *(const float4*)(w + s);
#pragma unroll
        for (int n = 0; n < NB; n++) {
            const float* pp = &ps[n * SD + s];
            acc[n] += wv.x * pp[0] + wv.y * pp[1] + wv.z * pp[2] + wv.w * pp[3];
        }
    }
    if (isk) {
#pragma unroll
        for (int n = 0; n < NB; n++) g_pwkn[(size_t)n * ODK + r] = acc[n] + bias;
    } else {
#pragma unroll
        for (int n = 0; n < NB; n++) g_pwbias[n * COUT + rr] = acc[n] + bias;
    }
}

// ---------------- K2: dk GEMM, M=32/warp, K-permuted LDG.128 A, K-split 4 ----------------
// Grid 1024 = 256 M-blocks (128 rows) x 4 K-quarters. 128 threads = 4 warps x 32 rows.
__global__ void __launch_bounds__(128) k_dk(const float* __restrict__ Wdk) {
    __shared__ __align__(16) uint4 Bs[3][BSTG];   // 3 x 4608 B

    int tid = threadIdx.x;
    int wid = tid >> 5, lane = tid & 31;
    int bx = blockIdx.x;
    int kq = bx & 3;
    int mb = bx >> 2;
    int m0 = mb * 128 + wid * 32;
    int rA = m0 + (lane >> 2);
    int q4 = (lane & 3) * 4;         // A mem-k offset (permuted, contiguous)
    int kc2 = (lane & 3) * 2;        // C column offset
    int sbase = kq * QSTEP;

    const float* aBase = Wdk + (size_t)rA * KDK + q4 + (size_t)sbase * 16;
    const size_t r8 = (size_t)8 * KDK;
    const uint4* bfrag0 = g_Bfrag + (size_t)sbase * BSTG;

    uint32_t bs_addr[3];
#pragma unroll
    for (int b = 0; b < 3; b++) bs_addr[b] = (uint32_t)__cvta_generic_to_shared(&Bs[b][0]);

    float acc[2][NTIL][4];
#pragma unroll
    for (int j = 0; j < 2; j++)
#pragma unroll
        for (int nt = 0; nt < NTIL; nt++)
#pragma unroll
            for (int q = 0; q < 4; q++) acc[j][nt][q] = 0.f;

    // ---- prologue: A steps 0,1 (4 LDG.128 each); B stages 0,1 via cp.async ----
    float4 pa[2][4];   // [buf][row-slot: rA, rA+8, rA+16, rA+24]
#pragma unroll
    for (int d = 0; d < 2; d++) {
        const float* ap = aBase + (size_t)d * 16;
        pa[d][0] = *(const float4*)(ap);
        pa[d][1] = *(const float4*)(ap + r8);
        pa[d][2] = *(const float4*)(ap + 2 * r8);
        pa[d][3] = *(const float4*)(ap + 3 * r8);
    }
#pragma unroll
    for (int st = 0; st < 2; st++) {
        const uint4* src = bfrag0 + (size_t)st * BSTG;
        cp16(bs_addr[st] + tid * 16, src + tid);
        cp16(bs_addr[st] + (tid + 128) * 16, src + tid + 128);
        if (tid < 32) cp16(bs_addr[st] + (tid + 256) * 16, src + tid + 256);
        CP_COMMIT();
    }
    CP_WAIT1();
    __syncthreads();

    for (int s = 0; s < QSTEP; s++) {
        int cb = s & 1;
        // convert A(s): two fragment sets
        uint32_t ahi[2][4], alo[2][4];
#pragma unroll
        for (int j = 0; j < 2; j++) {
            float4 fr = pa[cb][2 * j];       // row rA + 16j
            float4 f8 = pa[cb][2 * j + 1];   // row rA + 16j + 8
            __nv_bfloat162 h0 = __floats2bfloat162_rn(fr.x, fr.y);
            __nv_bfloat162 h1 = __floats2bfloat162_rn(f8.x, f8.y);
            __nv_bfloat162 h2 = __floats2bfloat162_rn(fr.z, fr.w);
            __nv_bfloat162 h3 = __floats2bfloat162_rn(f8.z, f8.w);
            ahi[j][0] = bf2u(h0); ahi[j][1] = bf2u(h1); ahi[j][2] = bf2u(h2); ahi[j][3] = bf2u(h3);
            alo[j][0] = bf2u(__floats2bfloat162_rn(fr.x - __low2float(h0), fr.y - __high2float(h0)));
            alo[j][1] = bf2u(__floats2bfloat162_rn(f8.x - __low2float(h1), f8.y - __high2float(h1)));
            alo[j][2] = bf2u(__floats2bfloat162_rn(fr.z - __low2float(h2), fr.w - __high2float(h2)));
            alo[j][3] = bf2u(__floats2bfloat162_rn(f8.z - __low2float(h3), f8.w - __high2float(h3)));
        }
        // prefetch A(s+2) into the buffer we just consumed
        if (s + 2 < QSTEP) {
            const float* ap = aBase + (size_t)(s + 2) * 16;
            pa[cb][0] = *(const float4*)(ap);
            pa[cb][1] = *(const float4*)(ap + r8);
            pa[cb][2] = *(const float4*)(ap + 2 * r8);
            pa[cb][3] = *(const float4*)(ap + 3 * r8);
        }
        // B stage s+2 via cp.async
        if (s + 2 < QSTEP) {
            int nb = (s + 2) % 3;
            const uint4* src = bfrag0 + (size_t)(s + 2) * BSTG;
            cp16(bs_addr[nb] + tid * 16, src + tid);
            cp16(bs_addr[nb] + (tid + 128) * 16, src + tid + 128);
            if (tid < 32) cp16(bs_addr[nb] + (tid + 256) * 16, src + tid + 256);
        }
        CP_COMMIT();
        // MMAs: 9 B loads feed 54 MMAs (2 row-sets x 3 split-terms)
        const uint4* bsrow = &Bs[s % 3][lane];
#pragma unroll
        for (int nt = 0; nt < NTIL; nt++) {
            uint4 b = bsrow[nt * 32];
            mma16816(acc[0][nt], ahi[0], b.x, b.y);
            mma16816(acc[0][nt], ahi[0], b.z, b.w);
            mma16816(acc[0][nt], alo[0], b.x, b.y);
            mma16816(acc[1][nt], ahi[1], b.x, b.y);
            mma16816(acc[1][nt], ahi[1], b.z, b.w);
            mma16816(acc[1][nt], alo[1], b.x, b.y);
        }
        CP_WAIT1();
        __syncthreads();
    }

    // epilogue: partials (no bias; k_red adds it)
    float* dst = g_dwP[kq];
#pragma unroll
    for (int j = 0; j < 2; j++) {
        int o0 = rA + 16 * j, o1 = o0 + 8;
        int co0 = o0 >> 6, ci0 = o0 & 63;
        int co1 = o1 >> 6, ci1 = o1 & 63;
#pragma unroll
        for (int nt = 0; nt < NTIL; nt++) {
            int colb = nt * 8 + kc2;
#pragma unroll
            for (int d = 0; d < 2; d++) {
                int col = colb + d;
                int n = col / 9, jj = col % 9;
                dst[((size_t)((n * CPG + ci0) * 9 + jj)) * COUT + co0] = acc[j][nt][d];
                dst[((size_t)((n * CPG + ci1) * 9 + jj)) * COUT + co1] = acc[j][nt][2 + d];
            }
        }
    }
}

// ---------------- K2b: merge K-quarter partials + bias ----------------
__global__ void __launch_bounds__(256) k_red(const float* __restrict__ bdk) {
    int i = blockIdx.x * 256 + threadIdx.x;
    if (i >= DWSZ) return;
    int co = i & 511;
    int ci = (i / (9 * 512)) & 63;
    float b = bdk[co * 64 + ci];
    g_dwT[i] = g_dwP[0][i] + g_dwP[1][i] + g_dwP[2][i] + g_dwP[3][i] + b;
}

// ---------------- K3: fused depthwise+pointwise ----------------
#define IN_OFF   (CPG * 4 * WW)
#define BUFSZ    816
#define PW_OFF   (IN_OFF + 2 * BUFSZ)
#define SMEM_CONV ((PW_OFF + CPG * CPG) * 4)

__device__ __forceinline__ int refl(int i) {
    return i < 0 ? -i : (i > 63 ? 126 - i : i);
}

__global__ void __launch_bounds__(256, 2) k_conv(const float* __restrict__ pred, float* __restrict__ out) {
    extern __shared__ __align__(16) float sm[];
    float* depth_s = sm;
    float* in_base = sm + IN_OFF;
    float* pw_s    = sm + PW_OFF;

    int tid = threadIdx.x;
    int co = tid & 63;
    int hl = tid >> 6;
    int rb = blockIdx.x, g = blockIdx.y, n = blockIdx.z;
    int h0 = rb * 4;

    const float* base = pred + (size_t)(n * CIN + g * CPG) * HWSZ;

    for (int i = tid; i < CPG * CPG; i += 256) {
        int cm = i >> 6, c = i & 63;
        pw_s[i] = g_pwkn[(size_t)n * ODK + (g * CPG + c) * CPG + cm];
    }

    int i0 = tid, i1 = tid + 256;
    int r0 = i0 / 66, c0p = i0 % 66;
    int r1 = i1 / 66, c1p = i1 % 66;
    bool v1 = (i1 < 396);
    int goff0 = refl(h0 + r0 - 1) * WW + refl(c0p - 1);
    int goff1 = v1 ? (refl(h0 + r1 - 1) * WW + refl(c1p - 1)) : 0;
    int s0 = r0 * 68 + c0p;
    int s1 = r1 * 68 + c1p;

    float q0 = base[goff0];
    float q1 = v1 ? base[goff1] : 0.f;
    const float* wp = g_dwT + ((size_t)(n * CPG) * 9) * COUT + (g * CPG + co);
    float dcur[9], dnxt[9];
#pragma unroll
    for (int k = 0; k < 9; k++) dcur[k] = wp[k * COUT];

    ull acc2[32];
#pragma unroll
    for (int i = 0; i < 32; i++) acc2[i] = 0ULL;

    for (int ci = 0; ci < CPG; ci++) {
        float* ia = in_base + (ci & 1) * BUFSZ;
        float* ib = ia + 408;
        ia[s0] = q0;
        if (c0p) ib[s0 - 1] = q0;
        if (v1) {
            ia[s1] = q1;
            if (c1p) ib[s1 - 1] = q1;
        }
        __syncthreads();

        if (ci + 1 < CPG) {
            const float* pl = base + (size_t)(ci + 1) * HWSZ;
            q0 = pl[goff0];
            q1 = v1 ? pl[goff1] : 0.f;
            const float* wn = wp + (size_t)(ci + 1) * 9 * COUT;
#pragma unroll
            for (int k = 0; k < 9; k++) dnxt[k] = wn[k * COUT];
        }

#pragma unroll
        for (int kh = 0; kh < 3; kh++) {
            const float* row  = &ia[(hl + kh) * 68];
            const float* rowB = row + 408;
            ull w0 = pk2(dcur[kh * 3 + 0], dcur[kh * 3 + 0]);
            ull w1 = pk2(dcur[kh * 3 + 1], dcur[kh * 3 + 1]);
            ull w2 = pk2(dcur[kh * 3 + 2], dcur[kh * 3 + 2]);
#pragma unroll
            for (int c0 = 0; c0 < 64; c0 += 16) {
                const ull* ra = (const ull*)(row + c0);
                ulonglong2 a01 = *(const ulonglong2*)(ra);
                ulonglong2 a23 = *(const ulonglong2*)(ra + 2);
                ulonglong2 a45 = *(const ulonglong2*)(ra + 4);
                ulonglong2 a67 = *(const ulonglong2*)(ra + 6);
                ull a8 = ra[8];
                const ull* rbp = (const ull*)(rowB + c0);
                ulonglong2 b01 = *(const ulonglong2*)(rbp);
                ulonglong2 b23 = *(const ulonglong2*)(rbp + 2);
                ulonglong2 b45 = *(const ulonglong2*)(rbp + 4);
                ulonglong2 b67 = *(const ulonglong2*)(rbp + 6);
                int p = c0 >> 1;
                fma2(acc2[p + 0], w0, a01.x); fma2(acc2[p + 0], w1, b01.x); fma2(acc2[p + 0], w2, a01.y);
                fma2(acc2[p + 1], w0, a01.y); fma2(acc2[p + 1], w1, b01.y); fma2(acc2[p + 1], w2, a23.x);
                fma2(acc2[p + 2], w0, a23.x); fma2(acc2[p + 2], w1, b23.x); fma2(acc2[p + 2], w2, a23.y);
                fma2(acc2[p + 3], w0, a23.y); fma2(acc2[p + 3], w1, b23.y); fma2(acc2[p + 3], w2, a45.x);
                fma2(acc2[p + 4], w0, a45.x); fma2(acc2[p + 4], w1, b45.x); fma2(acc2[p + 4], w2, a45.y);
                fma2(acc2[p + 5], w0, a45.y); fma2(acc2[p + 5], w1, b45.y); fma2(acc2[p + 5], w2, a67.x);
                fma2(acc2[p + 6], w0, a67.x); fma2(acc2[p + 6], w1, b67.x); fma2(acc2[p + 6], w2, a67.y);
                fma2(acc2[p + 7], w0, a67.y); fma2(acc2[p + 7], w1, b67.y); fma2(acc2[p + 7], w2, a8);
            }
        }
#pragma unroll
        for (int k = 0; k < 9; k++) dcur[k] = dnxt[k];
    }

    __syncthreads();
    {
        ull* dst = (ull*)(depth_s + (co * 4 + hl) * 64);
#pragma unroll
        for (int i = 0; i < 32; i++) dst[i] = acc2[i];
    }
    __syncthreads();

#pragma unroll
    for (int i = 0; i < 32; i++) acc2[i] = 0ULL;
    for (int cm = 0; cm < CPG; cm++) {
        float v = pw_s[cm * 64 + co];
        ull vp = pk2(v, v);
        const ulonglong2* ds = (const ulonglong2*)(depth_s + (cm * 4 + hl) * 64);
#pragma unroll
        for (int i = 0; i < 16; i++) {
            ulonglong2 t = ds[i];
            fma2(acc2[2 * i],     vp, t.x);
            fma2(acc2[2 * i + 1], vp, t.y);
        }
    }

    float bias = g_pwbias[n * COUT + g * CPG + co];
    float* op = out + (((size_t)(n * COUT + g * CPG + co)) * HH + (h0 + hl)) * WW;
#pragma unroll
    for (int i = 0; i < 16; i++) {
        float x0, x1, x2, x3;
        upk2(acc2[2 * i], x0, x1);
        upk2(acc2[2 * i + 1], x2, x3);
        *(float4*)(op + 4 * i) = make_float4(x0 + bias, x1 + bias, x2 + bias, x3 + bias);
    }
}

// ---------------- Launch ----------------
extern "C" void kernel_launch(void* const* d_in, const int* in_sizes, int n_in,
                              void* d_out, int out_size) {
    const float* style = (const float*)d_in[0];
    const float* pred  = (const float*)d_in[1];
    const float* Wdk   = (const float*)d_in[2];
    const float* bdk   = (const float*)d_in[3];
    const float* Wpwk  = (const float*)d_in[4];
    const float* bpwk  = (const float*)d_in[5];
    const float* Wpwb  = (const float*)d_in[6];
    const float* bpwb  = (const float*)d_in[7];
    float* out = (float*)d_out;

    cudaFuncSetAttribute(k_conv, cudaFuncAttributeMaxDynamicSharedMemorySize, SMEM_CONV);

    k_pool<<<(NB * SD + 255) / 256, 256>>>(style);
    k_buildB<<<(NSTEP * NTIL * 32 + 255) / 256, 256>>>(style);
    k_pw<<<(ODK + COUT + 255) / 256, 256>>>(Wpwk, bpwk, Wpwb, bpwb);
    k_dk<<<(ODK / 128) * KSPLIT, 128>>>(Wdk);
    k_red<<<(DWSZ + 255) / 256, 256>>>(bdk);
    k_conv<<<dim3(HH / 4, NG, NB), 256, SMEM_CONV>>>(pred, out);
}